// round 1
// baseline (speedup 1.0000x reference)
#include <cuda_runtime.h>

#define NQ  16
#define DIM 65536
#define NB  64
#define NC  23
#define TPB 512
#define LOC 16384   // 2^14 amps per tile

__device__ float2 g_state[NB * DIM];   // 32 MB scratch
__device__ float  g_expv[NB * NQ];

__device__ __forceinline__ float2 cmulf(float2 a, float2 b){
    return make_float2(a.x*b.x - a.y*b.y, a.x*b.y + a.y*b.x);
}
__device__ __forceinline__ void ap1q(float2 &v0, float2 &v1,
                                     float2 u00, float2 u01, float2 u10, float2 u11){
    float2 a = v0, b = v1;
    v0.x = u00.x*a.x - u00.y*a.y + u01.x*b.x - u01.y*b.y;
    v0.y = u00.x*a.y + u00.y*a.x + u01.x*b.y + u01.y*b.x;
    v1.x = u10.x*a.x - u10.y*a.y + u11.x*b.x - u11.y*b.y;
    v1.y = u10.x*a.y + u10.y*a.x + u11.x*b.y + u11.y*b.x;
}
// RX(theta): [[c, -i s], [-i s, c]]
__device__ __forceinline__ void aprx(float2 &v0, float2 &v1, float c, float s){
    float2 a = v0, b = v1;
    v0 = make_float2(fmaf(c, a.x,  s*b.y), fmaf(c, a.y, -s*b.x));
    v1 = make_float2(fmaf(c, b.x,  s*a.y), fmaf(c, b.y, -s*a.x));
}
__device__ __forceinline__ int SW(int l){ return l ^ ((l >> 4) & 15); }

// Fused U = Rot(w) * RX(x[b,q]); CRX params (cos, sin) of half-angle.
__device__ __forceinline__ void setup_gates(const float* __restrict__ x,
                                            const float* __restrict__ w,
                                            const float* __restrict__ xc,
                                            int b, float2 (*sU)[4], float2* sCX){
    int tid = threadIdx.x;
    if (tid < NQ){
        int q = tid;
        float xv = x[b*NQ + q];
        float hc = cosf(0.5f*xv), hs = sinf(0.5f*xv);
        float phi = w[q*3+0], th = w[q*3+1], om = w[q*3+2];
        float ct = cosf(0.5f*th), st = sinf(0.5f*th);
        float pp = 0.5f*(phi+om), mm = 0.5f*(phi-om);
        float2 A  = make_float2( cosf(pp)*ct, -sinf(pp)*ct);
        float2 Bm = make_float2(-cosf(mm)*st, -sinf(mm)*st);
        float2 C  = make_float2( cosf(mm)*st, -sinf(mm)*st);
        float2 D  = make_float2( cosf(pp)*ct,  sinf(pp)*ct);
        sU[q][0] = make_float2(A.x*hc + Bm.y*hs,   A.y*hc - Bm.x*hs);
        sU[q][1] = make_float2(A.y*hs + Bm.x*hc,  -A.x*hs + Bm.y*hc);
        sU[q][2] = make_float2(C.x*hc + D.y*hs,    C.y*hc - D.x*hs);
        sU[q][3] = make_float2(C.y*hs + D.x*hc,   -C.x*hs + D.y*hc);
        float cv = xc[q];
        sCX[q] = make_float2(cosf(0.5f*cv), sinf(0.5f*cv));
    }
}

template<int N, int K>
__device__ __forceinline__ void set_1q(float2* v, const float2* u){
    float2 u00 = u[0], u01 = u[1], u10 = u[2], u11 = u[3];
    #pragma unroll
    for (int m = 0; m < N; m++)
        if (!(m & (1 << K))) ap1q(v[m], v[m | (1 << K)], u00, u01, u10, u11);
}
template<int N, int KC, int KT>
__device__ __forceinline__ void set_crx(float2* v, float2 cs){
    #pragma unroll
    for (int m = 0; m < N; m++)
        if ((m & (1 << KC)) && !(m & (1 << KT)))
            aprx(v[m], v[m | (1 << KT)], cs.x, cs.y);
}

// ---------------------------------------------------------------------------
// Pass 1: local amp bits {15..6, 3..0}, fixed tile bits {5,4}.
// Gates: 1q wires 0..9, 12..15 ; CRX 0,1,2.  amp i = (l&15)|(t<<4)|((l>>4)<<6)
// first=1: build product state analytically (tile 0), zero tiles 1..3,
//          rounds apply only CRX (1q already in the product).
// ---------------------------------------------------------------------------
__global__ void __launch_bounds__(TPB, 1)
pass1_kernel(const float* __restrict__ x, const float* __restrict__ w,
             const float* __restrict__ xc, int first){
    extern __shared__ float2 S[];
    __shared__ float2 sU[NQ][4];
    __shared__ float2 sCX[NQ];
    int tid = threadIdx.x;
    int t   = blockIdx.x;
    int b   = blockIdx.y;
    int base_g = b * DIM;

    if (first && t != 0){
        float4 z = make_float4(0.f, 0.f, 0.f, 0.f);
        for (int l = tid*2; l < LOC; l += TPB*2){
            int i = (l & 15) | (t << 4) | ((l >> 4) << 6);
            *(float4*)&g_state[base_g + i] = z;
        }
        return;
    }

    setup_gates(x, w, xc, b, sU, sCX);
    if (first && tid < NQ) g_expv[b*NQ + tid] = 0.f;   // reset per replay
    __syncthreads();

    if (first){
        // product state over the 14 pass-1 wires (bits 5,4 == 0 in tile 0)
        for (int l = tid; l < LOC; l += TPB){
            float2 a = make_float2(1.f, 0.f);
            #pragma unroll
            for (int k = 0; k < 14; k++){
                int wire = (k < 4) ? (15 - k) : (13 - k);
                int bit  = (l >> k) & 1;
                a = cmulf(a, sU[wire][bit ? 2 : 0]);   // column 0 of U
            }
            S[SW(l)] = a;
        }
    } else {
        for (int l = tid*2; l < LOC; l += TPB*2){
            int i = (l & 15) | (t << 4) | ((l >> 4) << 6);
            float4 vv = *(const float4*)&g_state[base_g + i];
            S[SW(l)]     = make_float2(vv.x, vv.y);
            S[SW(l | 1)] = make_float2(vv.z, vv.w);
        }
    }
    __syncthreads();

    // Round 1: local bits p13..p10 (wires 0..3) + CRX0,1,2
    for (int j = tid; j < 1024; j += TPB){
        int base = j;                         // bb=10
        float2 v[16];
        #pragma unroll
        for (int m = 0; m < 16; m++) v[m] = S[SW(base | (m << 10))];
        if (!first){
            set_1q<16,3>(v, sU[0]);
            set_1q<16,2>(v, sU[1]);
            set_1q<16,1>(v, sU[2]);
            set_1q<16,0>(v, sU[3]);
        }
        set_crx<16,3,2>(v, sCX[0]);
        set_crx<16,2,1>(v, sCX[1]);
        set_crx<16,1,0>(v, sCX[2]);
        #pragma unroll
        for (int m = 0; m < 16; m++) S[SW(base | (m << 10))] = v[m];
    }
    __syncthreads();

    if (!first){
        // Round 2: bits p9..p7 (wires 4,5,6)
        for (int j = tid; j < 2048; j += TPB){
            int base = (j & 127) | ((j >> 7) << 10);
            float2 v[8];
            #pragma unroll
            for (int m = 0; m < 8; m++) v[m] = S[SW(base | (m << 7))];
            set_1q<8,2>(v, sU[4]);
            set_1q<8,1>(v, sU[5]);
            set_1q<8,0>(v, sU[6]);
            #pragma unroll
            for (int m = 0; m < 8; m++) S[SW(base | (m << 7))] = v[m];
        }
        __syncthreads();
        // Round 3: bits p6..p4 (wires 7,8,9)
        for (int j = tid; j < 2048; j += TPB){
            int base = (j & 15) | ((j >> 4) << 7);
            float2 v[8];
            #pragma unroll
            for (int m = 0; m < 8; m++) v[m] = S[SW(base | (m << 4))];
            set_1q<8,2>(v, sU[7]);
            set_1q<8,1>(v, sU[8]);
            set_1q<8,0>(v, sU[9]);
            #pragma unroll
            for (int m = 0; m < 8; m++) S[SW(base | (m << 4))] = v[m];
        }
        __syncthreads();
        // Round 4: bits p3..p0 (wires 12..15)
        for (int j = tid; j < 1024; j += TPB){
            int base = j << 4;
            float2 v[16];
            #pragma unroll
            for (int m = 0; m < 16; m++) v[m] = S[SW(base | m)];
            set_1q<16,3>(v, sU[12]);
            set_1q<16,2>(v, sU[13]);
            set_1q<16,1>(v, sU[14]);
            set_1q<16,0>(v, sU[15]);
            #pragma unroll
            for (int m = 0; m < 16; m++) S[SW(base | m)] = v[m];
        }
        __syncthreads();
    }

    for (int l = tid*2; l < LOC; l += TPB*2){
        int i = (l & 15) | (t << 4) | ((l >> 4) << 6);
        float2 a = S[SW(l)], c2 = S[SW(l | 1)];
        *(float4*)&g_state[base_g + i] = make_float4(a.x, a.y, c2.x, c2.y);
    }
}

// ---------------------------------------------------------------------------
// Pass 2: local amp bits {15, 12..0}, fixed tile bits {14,13}.
// Gates: 1q wires 10,11 ; CRX 3..15 (CRX15 wraps: ctrl bit0 -> tgt bit15).
// amp i = (l&0x1FFF)|(t<<13)|((l>>13)<<15);  local p13 <-> amp bit 15.
// last=1: compute PauliZ expvals instead of storing the state.
// ---------------------------------------------------------------------------
__global__ void __launch_bounds__(TPB, 1)
pass2_kernel(const float* __restrict__ x, const float* __restrict__ w,
             const float* __restrict__ xc, int last){
    extern __shared__ float2 S[];
    __shared__ float2 sU[NQ][4];
    __shared__ float2 sCX[NQ];
    int tid = threadIdx.x;
    int t   = blockIdx.x;
    int b   = blockIdx.y;
    int base_g = b * DIM;

    setup_gates(x, w, xc, b, sU, sCX);
    __syncthreads();

    for (int l = tid*2; l < LOC; l += TPB*2){
        int i = (l & 0x1FFF) | (t << 13) | ((l >> 13) << 15);
        float4 vv = *(const float4*)&g_state[base_g + i];
        S[SW(l)]     = make_float2(vv.x, vv.y);
        S[SW(l | 1)] = make_float2(vv.z, vv.w);
    }
    __syncthreads();

    // RB: bits p12..p9 : CRX3,4,5
    for (int j = tid; j < 1024; j += TPB){
        int base = (j & 511) | ((j >> 9) << 13);
        float2 v[16];
        #pragma unroll
        for (int m = 0; m < 16; m++) v[m] = S[SW(base | (m << 9))];
        set_crx<16,3,2>(v, sCX[3]);
        set_crx<16,2,1>(v, sCX[4]);
        set_crx<16,1,0>(v, sCX[5]);
        #pragma unroll
        for (int m = 0; m < 16; m++) S[SW(base | (m << 9))] = v[m];
    }
    __syncthreads();
    // RC: bits p9..p6 : CRX6,7,8
    for (int j = tid; j < 1024; j += TPB){
        int base = (j & 63) | ((j >> 6) << 10);
        float2 v[16];
        #pragma unroll
        for (int m = 0; m < 16; m++) v[m] = S[SW(base | (m << 6))];
        set_crx<16,3,2>(v, sCX[6]);
        set_crx<16,2,1>(v, sCX[7]);
        set_crx<16,1,0>(v, sCX[8]);
        #pragma unroll
        for (int m = 0; m < 16; m++) S[SW(base | (m << 6))] = v[m];
    }
    __syncthreads();
    // RD: bits p6..p3 : 1q w10 (p5), w11 (p4), then CRX9,10,11
    for (int j = tid; j < 1024; j += TPB){
        int base = (j & 7) | ((j >> 3) << 7);
        float2 v[16];
        #pragma unroll
        for (int m = 0; m < 16; m++) v[m] = S[SW(base | (m << 3))];
        set_1q<16,2>(v, sU[10]);
        set_1q<16,1>(v, sU[11]);
        set_crx<16,3,2>(v, sCX[9]);
        set_crx<16,2,1>(v, sCX[10]);
        set_crx<16,1,0>(v, sCX[11]);
        #pragma unroll
        for (int m = 0; m < 16; m++) S[SW(base | (m << 3))] = v[m];
    }
    __syncthreads();
    // RE: bits p3..p0 : CRX12,13,14
    for (int j = tid; j < 1024; j += TPB){
        int base = j << 4;
        float2 v[16];
        #pragma unroll
        for (int m = 0; m < 16; m++) v[m] = S[SW(base | m)];
        set_crx<16,3,2>(v, sCX[12]);
        set_crx<16,2,1>(v, sCX[13]);
        set_crx<16,1,0>(v, sCX[14]);
        #pragma unroll
        for (int m = 0; m < 16; m++) S[SW(base | m)] = v[m];
    }
    __syncthreads();
    // RF: CRX15 : ctrl local bit0 (=amp bit0, wire15), tgt local p13 (=amp bit15, wire0)
    {
        float2 cs15 = sCX[15];
        for (int j = tid; j < 4096; j += TPB){
            int l0 = (j << 1) | 1;        // bit0 = 1 (control), bit13 = 0
            int l1 = l0 | (1 << 13);
            float2 v0 = S[SW(l0)], v1 = S[SW(l1)];
            aprx(v0, v1, cs15.x, cs15.y);
            S[SW(l0)] = v0; S[SW(l1)] = v1;
        }
    }
    __syncthreads();

    if (!last){
        for (int l = tid*2; l < LOC; l += TPB*2){
            int i = (l & 0x1FFF) | (t << 13) | ((l >> 13) << 15);
            float2 a = S[SW(l)], c2 = S[SW(l | 1)];
            *(float4*)&g_state[base_g + i] = make_float4(a.x, a.y, c2.x, c2.y);
        }
    } else {
        float acc[NQ];
        #pragma unroll
        for (int q = 0; q < NQ; q++) acc[q] = 0.f;
        for (int l = tid; l < LOC; l += TPB){
            float2 a = S[SW(l)];
            float p = a.x*a.x + a.y*a.y;
            int i = (l & 0x1FFF) | (t << 13) | ((l >> 13) << 15);
            #pragma unroll
            for (int q = 0; q < NQ; q++)
                acc[q] += ((i >> (15 - q)) & 1) ? -p : p;
        }
        #pragma unroll
        for (int q = 0; q < NQ; q++){
            float v = acc[q];
            #pragma unroll
            for (int off = 16; off > 0; off >>= 1)
                v += __shfl_down_sync(0xffffffffu, v, off);
            if ((tid & 31) == 0) atomicAdd(&g_expv[b*NQ + q], v);
        }
    }
}

__global__ void fc_kernel(const float* __restrict__ fc_w, const float* __restrict__ fc_b,
                          float* __restrict__ out){
    int b = threadIdx.x;
    if (b >= NB) return;
    float f[NQ];
    #pragma unroll
    for (int q = 0; q < NQ; q++) f[q] = g_expv[b*NQ + q];
    float lg[NC];
    float mx = -1e30f;
    #pragma unroll
    for (int c = 0; c < NC; c++){
        float s = fc_b[c];
        #pragma unroll
        for (int q = 0; q < NQ; q++) s = fmaf(fc_w[c*NQ + q], f[q], s);
        lg[c] = s;
        mx = fmaxf(mx, s);
    }
    float se = 0.f;
    #pragma unroll
    for (int c = 0; c < NC; c++) se += expf(lg[c] - mx);
    float ls = logf(se);
    #pragma unroll
    for (int c = 0; c < NC; c++) out[b*NC + c] = lg[c] - mx - ls;
}

extern "C" void kernel_launch(void* const* d_in, const int* in_sizes, int n_in,
                              void* d_out, int out_size){
    const float* x   = (const float*)d_in[0];
    const float* w0  = (const float*)d_in[1];
    const float* x0  = (const float*)d_in[2];
    const float* w1  = (const float*)d_in[3];
    const float* x1  = (const float*)d_in[4];
    const float* fcw = (const float*)d_in[5];
    const float* fcb = (const float*)d_in[6];

    size_t smem = (size_t)LOC * sizeof(float2);   // 128 KB
    cudaFuncSetAttribute(pass1_kernel, cudaFuncAttributeMaxDynamicSharedMemorySize, (int)smem);
    cudaFuncSetAttribute(pass2_kernel, cudaFuncAttributeMaxDynamicSharedMemorySize, (int)smem);

    dim3 grid(4, NB);
    pass1_kernel<<<grid, TPB, smem>>>(x, w0, x0, 1);
    pass2_kernel<<<grid, TPB, smem>>>(x, w0, x0, 0);
    pass1_kernel<<<grid, TPB, smem>>>(x, w1, x1, 0);
    pass2_kernel<<<grid, TPB, smem>>>(x, w1, x1, 1);
    fc_kernel<<<1, 64>>>(fcw, fcb, (float*)d_out);
}

// round 3
// speedup vs baseline: 1.1807x; 1.1807x over previous
#include <cuda_runtime.h>

#define NQ  16
#define DIM 65536
#define NB  64
#define NC  23
#define TPB 256
#define LOC 8192    // 2^13 amps per tile (64 KB)

__device__ float2 g_state[NB * DIM];   // 32 MB scratch
__device__ float  g_expv[NB * NQ];

__device__ __forceinline__ float2 cmulf(float2 a, float2 b){
    return make_float2(a.x*b.x - a.y*b.y, a.x*b.y + a.y*b.x);
}
__device__ __forceinline__ void ap1q(float2 &v0, float2 &v1,
                                     float2 u00, float2 u01, float2 u10, float2 u11){
    float2 a = v0, b = v1;
    v0.x = u00.x*a.x - u00.y*a.y + u01.x*b.x - u01.y*b.y;
    v0.y = u00.x*a.y + u00.y*a.x + u01.x*b.y + u01.y*b.x;
    v1.x = u10.x*a.x - u10.y*a.y + u11.x*b.x - u11.y*b.y;
    v1.y = u10.x*a.y + u10.y*a.x + u11.x*b.y + u11.y*b.x;
}
// RX(theta): [[c, -i s], [-i s, c]] with c=cos(t/2), s=sin(t/2)
__device__ __forceinline__ void aprx(float2 &v0, float2 &v1, float c, float s){
    float2 a = v0, b = v1;
    v0 = make_float2(fmaf(c, a.x,  s*b.y), fmaf(c, a.y, -s*b.x));
    v1 = make_float2(fmaf(c, b.x,  s*a.y), fmaf(c, b.y, -s*a.x));
}
__device__ __forceinline__ int SW(int l){ return l ^ ((l >> 4) & 15); }

// Fused U = Rot(w[q]) * RX(x[b,q]); CRX params (cos, sin) of half-angle.
__device__ __forceinline__ void setup_one(const float* __restrict__ x,
                                          const float* __restrict__ w,
                                          const float* __restrict__ xc,
                                          int b, int q, float2 (*sU)[4], float2* sCX){
    float xv = x[b*NQ + q];
    float hc = cosf(0.5f*xv), hs = sinf(0.5f*xv);
    float phi = w[q*3+0], th = w[q*3+1], om = w[q*3+2];
    float ct = cosf(0.5f*th), st = sinf(0.5f*th);
    float pp = 0.5f*(phi+om), mm = 0.5f*(phi-om);
    float2 A  = make_float2( cosf(pp)*ct, -sinf(pp)*ct);
    float2 Bm = make_float2(-cosf(mm)*st, -sinf(mm)*st);
    float2 C  = make_float2( cosf(mm)*st, -sinf(mm)*st);
    float2 D  = make_float2( cosf(pp)*ct,  sinf(pp)*ct);
    sU[q][0] = make_float2(A.x*hc + Bm.y*hs,   A.y*hc - Bm.x*hs);
    sU[q][1] = make_float2(A.y*hs + Bm.x*hc,  -A.x*hs + Bm.y*hc);
    sU[q][2] = make_float2(C.x*hc + D.y*hs,    C.y*hc - D.x*hs);
    sU[q][3] = make_float2(C.y*hs + D.x*hc,   -C.x*hs + D.y*hc);
    float cv = xc[q];
    sCX[q] = make_float2(cosf(0.5f*cv), sinf(0.5f*cv));
}

template<int N, int K>
__device__ __forceinline__ void set_1q(float2* v, const float2* u){
    float2 u00 = u[0], u01 = u[1], u10 = u[2], u11 = u[3];
    #pragma unroll
    for (int m = 0; m < N; m++)
        if (!(m & (1 << K))) ap1q(v[m], v[m | (1 << K)], u00, u01, u10, u11);
}
template<int N, int KC, int KT>
__device__ __forceinline__ void set_crx(float2* v, float2 cs){
    #pragma unroll
    for (int m = 0; m < N; m++)
        if ((m & (1 << KC)) && !(m & (1 << KT)))
            aprx(v[m], v[m | (1 << KT)], cs.x, cs.y);
}

// ---------------------------------------------------------------------------
// K1: analytic product state (L1 1q on wires 0..9,12..15; wires 10,11 stay |0>)
//     + CRX0,1,2 (L1).  Tiling: local amp bits {15..12, 8..0}, fixed {11,10,9}.
//     amp i = s | (t<<9) | (m<<12),   s = bits 8..0, m = bits 15..12.
//     Pure write kernel (tables in smem, no state tile).
// ---------------------------------------------------------------------------
__global__ void __launch_bounds__(TPB)
k1_init(const float* __restrict__ x, const float* __restrict__ w0,
        const float* __restrict__ x0){
    __shared__ float2 sU[NQ][4];
    __shared__ float2 sCX[NQ];
    __shared__ float2 Tlo[512];
    __shared__ float2 Thi[16];
    int tid = threadIdx.x, t = blockIdx.x, b = blockIdx.y;
    if (tid < 16) setup_one(x, w0, x0, b, tid, sU, sCX);
    if (t == 0 && tid < NQ) g_expv[b*NQ + tid] = 0.f;   // reset per replay
    __syncthreads();
    // Tlo over amp bits 8..0 (wires 7..15); wires 10,11 (bits 5,4) -> |0>
    for (int s = tid; s < 512; s += TPB){
        float2 a = make_float2(1.f, 0.f);
        #pragma unroll
        for (int k = 0; k < 9; k++){
            int wire = 15 - k;
            int bit  = (s >> k) & 1;
            if (wire == 10 || wire == 11){ if (bit) a = make_float2(0.f, 0.f); }
            else a = cmulf(a, sU[wire][bit ? 2 : 0]);
        }
        Tlo[s] = a;
    }
    if (tid < 16){
        int m = tid;
        float2 a = sU[0][((m >> 3) & 1) ? 2 : 0];
        a = cmulf(a, sU[1][((m >> 2) & 1) ? 2 : 0]);
        a = cmulf(a, sU[2][((m >> 1) & 1) ? 2 : 0]);
        a = cmulf(a, sU[3][( m       & 1) ? 2 : 0]);
        a = cmulf(a, sU[4][((t >> 2) & 1) ? 2 : 0]);   // wire4 = amp bit 11
        a = cmulf(a, sU[5][((t >> 1) & 1) ? 2 : 0]);   // wire5 = amp bit 10
        a = cmulf(a, sU[6][( t       & 1) ? 2 : 0]);   // wire6 = amp bit 9
        Thi[m] = a;
    }
    __syncthreads();
    float2 cs0 = sCX[0], cs1 = sCX[1], cs2 = sCX[2];
    float2* gb = g_state + b*DIM + (t << 9);
    for (int s = tid; s < 512; s += TPB){
        float2 tlo = Tlo[s];
        float2 v[16];
        #pragma unroll
        for (int m = 0; m < 16; m++) v[m] = cmulf(Thi[m], tlo);
        // m bit3=wire0, bit2=wire1, bit1=wire2, bit0=wire3
        set_crx<16,3,2>(v, cs0);   // CRX0: 0->1
        set_crx<16,2,1>(v, cs1);   // CRX1: 1->2
        set_crx<16,1,0>(v, cs2);   // CRX2: 2->3
        #pragma unroll
        for (int m = 0; m < 16; m++) gb[s + (m << 12)] = v[m];
    }
}

// ---------------------------------------------------------------------------
// K2: PassB(L1). local amp bits 12..0, fixed {15,14,13} (t).  i = l | (t<<13)
// Rounds (local bit = amp bit):
//  r0 {12..9}:  CRX3,4,5 (L1)       + 1q L2 w3,w4,w5
//  r1 {9..6}:   CRX6,7,8 (L1)       + 1q L2 w6,w7,w8
//  r2 {6..3}:   1q L1 w10,w11; CRX9,10,11 (L1) + 1q L2 w9,w10,w11
//  r3 {3..0}:   CRX12,13,14 (L1)    + 1q L2 w12,w13,w14
// ---------------------------------------------------------------------------
__global__ void __launch_bounds__(TPB, 3)
k2_passB1(const float* __restrict__ x, const float* __restrict__ w0,
          const float* __restrict__ x0, const float* __restrict__ w1,
          const float* __restrict__ x1){
    extern __shared__ float2 S[];
    __shared__ float2 sU1[NQ][4], sU2[NQ][4];
    __shared__ float2 sCX1[NQ], sCX2[NQ];
    int tid = threadIdx.x, t = blockIdx.x, b = blockIdx.y;
    if (tid < 16)      setup_one(x, w0, x0, b, tid,      sU1, sCX1);
    else if (tid < 32) setup_one(x, w1, x1, b, tid - 16, sU2, sCX2);
    __syncthreads();

    const float2* gi = g_state + b*DIM + (t << 13);
    for (int l = tid*2; l < LOC; l += TPB*2){
        float4 vv = *(const float4*)(gi + l);
        S[SW(l)]   = make_float2(vv.x, vv.y);
        S[SW(l|1)] = make_float2(vv.z, vv.w);
    }
    __syncthreads();

    // r0: m0<->b9(w6), m1<->b10(w5), m2<->b11(w4), m3<->b12(w3)
    for (int g = tid; g < 512; g += TPB){
        int base = g;
        float2 v[16];
        #pragma unroll
        for (int m = 0; m < 16; m++) v[m] = S[SW(base | (m << 9))];
        set_crx<16,3,2>(v, sCX1[3]);
        set_crx<16,2,1>(v, sCX1[4]);
        set_crx<16,1,0>(v, sCX1[5]);
        set_1q<16,3>(v, sU2[3]);
        set_1q<16,2>(v, sU2[4]);
        set_1q<16,1>(v, sU2[5]);
        #pragma unroll
        for (int m = 0; m < 16; m++) S[SW(base | (m << 9))] = v[m];
    }
    __syncthreads();
    // r1: m0<->b6(w9), m1<->b7(w8), m2<->b8(w7), m3<->b9(w6)
    for (int g = tid; g < 512; g += TPB){
        int base = (g & 63) | ((g >> 6) << 10);
        float2 v[16];
        #pragma unroll
        for (int m = 0; m < 16; m++) v[m] = S[SW(base | (m << 6))];
        set_crx<16,3,2>(v, sCX1[6]);
        set_crx<16,2,1>(v, sCX1[7]);
        set_crx<16,1,0>(v, sCX1[8]);
        set_1q<16,3>(v, sU2[6]);
        set_1q<16,2>(v, sU2[7]);
        set_1q<16,1>(v, sU2[8]);
        #pragma unroll
        for (int m = 0; m < 16; m++) S[SW(base | (m << 6))] = v[m];
    }
    __syncthreads();
    // r2: m0<->b3(w12), m1<->b4(w11), m2<->b5(w10), m3<->b6(w9)
    for (int g = tid; g < 512; g += TPB){
        int base = (g & 7) | ((g >> 3) << 7);
        float2 v[16];
        #pragma unroll
        for (int m = 0; m < 16; m++) v[m] = S[SW(base | (m << 3))];
        set_1q<16,2>(v, sU1[10]);
        set_1q<16,1>(v, sU1[11]);
        set_crx<16,3,2>(v, sCX1[9]);
        set_crx<16,2,1>(v, sCX1[10]);
        set_crx<16,1,0>(v, sCX1[11]);
        set_1q<16,3>(v, sU2[9]);
        set_1q<16,2>(v, sU2[10]);
        set_1q<16,1>(v, sU2[11]);
        #pragma unroll
        for (int m = 0; m < 16; m++) S[SW(base | (m << 3))] = v[m];
    }
    __syncthreads();
    // r3: m0<->b0(w15), m1<->b1(w14), m2<->b2(w13), m3<->b3(w12)
    for (int g = tid; g < 512; g += TPB){
        int base = g << 4;
        float2 v[16];
        #pragma unroll
        for (int m = 0; m < 16; m++) v[m] = S[SW(base | m)];
        set_crx<16,3,2>(v, sCX1[12]);
        set_crx<16,2,1>(v, sCX1[13]);
        set_crx<16,1,0>(v, sCX1[14]);
        set_1q<16,3>(v, sU2[12]);
        set_1q<16,2>(v, sU2[13]);
        set_1q<16,1>(v, sU2[14]);
        #pragma unroll
        for (int m = 0; m < 16; m++) S[SW(base | m)] = v[m];
    }
    __syncthreads();

    float2* go = g_state + b*DIM + (t << 13);
    for (int l = tid*2; l < LOC; l += TPB*2){
        float2 a = S[SW(l)], c2 = S[SW(l|1)];
        *(float4*)(go + l) = make_float4(a.x, a.y, c2.x, c2.y);
    }
}

// ---------------------------------------------------------------------------
// K3: PassA(L2). local amp bits {15..12, 8..0}, fixed {11,10,9} (t).
//     i = (l & 0x1FF) | (t<<9) | ((l>>9)<<12)
// ra {b0, b15, b14, b13}: CRX15(L1), 1q L2 w15,w0,w1,w2, CRX0,1 (L2)
// rb {b13, b12}:          CRX2 (L2)
// ---------------------------------------------------------------------------
__global__ void __launch_bounds__(TPB, 3)
k3_passA2(const float* __restrict__ x, const float* __restrict__ x0,
          const float* __restrict__ w1, const float* __restrict__ x1){
    extern __shared__ float2 S[];
    __shared__ float2 sU2[NQ][4], sCX2[NQ];
    __shared__ float2 cs15;
    int tid = threadIdx.x, t = blockIdx.x, b = blockIdx.y;
    if (tid < 16) setup_one(x, w1, x1, b, tid, sU2, sCX2);
    else if (tid == 16){
        float cv = x0[15];
        cs15 = make_float2(cosf(0.5f*cv), sinf(0.5f*cv));
    }
    __syncthreads();

    const float2* gbase = g_state + b*DIM;
    for (int l = tid*2; l < LOC; l += TPB*2){
        int i = (l & 0x1FF) | (t << 9) | ((l >> 9) << 12);
        float4 vv = *(const float4*)(gbase + i);
        S[SW(l)]   = make_float2(vv.x, vv.y);
        S[SW(l|1)] = make_float2(vv.z, vv.w);
    }
    __syncthreads();

    // ra: m0<->l0 (amp0, w15), m1<->l10 (amp13, w2), m2<->l11 (amp14, w1), m3<->l12 (amp15, w0)
    {
        float2 c15 = cs15;
        for (int g = tid; g < 512; g += TPB){
            int base = ((g & 0xFF) << 1) | ((g >> 8) << 9);
            float2 v[16];
            #pragma unroll
            for (int m = 0; m < 16; m++){
                int l = base | (m & 1) | ((m >> 1) << 10);
                v[m] = S[SW(l)];
            }
            set_crx<16,0,3>(v, c15);       // CRX15 (L1): w15 -> w0
            set_1q<16,0>(v, sU2[15]);
            set_1q<16,3>(v, sU2[0]);
            set_1q<16,2>(v, sU2[1]);
            set_1q<16,1>(v, sU2[2]);
            set_crx<16,3,2>(v, sCX2[0]);   // CRX0 (L2): w0 -> w1
            set_crx<16,2,1>(v, sCX2[1]);   // CRX1 (L2): w1 -> w2
            #pragma unroll
            for (int m = 0; m < 16; m++){
                int l = base | (m & 1) | ((m >> 1) << 10);
                S[SW(l)] = v[m];
            }
        }
    }
    __syncthreads();
    // rb: m0<->l9 (amp12, w3), m1<->l10 (amp13, w2)
    for (int g = tid; g < 2048; g += TPB){
        int base = (g & 0x1FF) | ((g >> 9) << 11);
        float2 v[4];
        #pragma unroll
        for (int m = 0; m < 4; m++) v[m] = S[SW(base | (m << 9))];
        set_crx<4,1,0>(v, sCX2[2]);        // CRX2 (L2): w2 -> w3
        #pragma unroll
        for (int m = 0; m < 4; m++) S[SW(base | (m << 9))] = v[m];
    }
    __syncthreads();

    float2* go = g_state + b*DIM;
    for (int l = tid*2; l < LOC; l += TPB*2){
        int i = (l & 0x1FF) | (t << 9) | ((l >> 9) << 12);
        float2 a = S[SW(l)], c2 = S[SW(l|1)];
        *(float4*)(go + i) = make_float4(a.x, a.y, c2.x, c2.y);
    }
}

// ---------------------------------------------------------------------------
// K4: PassB(L2). Same tiling/rounds as K2 but CRX3..14 (L2) only.
// ---------------------------------------------------------------------------
__global__ void __launch_bounds__(TPB, 3)
k4_passB2(const float* __restrict__ x, const float* __restrict__ w1,
          const float* __restrict__ x1){
    extern __shared__ float2 S[];
    __shared__ float2 sU2[NQ][4], sCX2[NQ];
    int tid = threadIdx.x, t = blockIdx.x, b = blockIdx.y;
    if (tid < 16) setup_one(x, w1, x1, b, tid, sU2, sCX2);
    __syncthreads();

    const float2* gi = g_state + b*DIM + (t << 13);
    for (int l = tid*2; l < LOC; l += TPB*2){
        float4 vv = *(const float4*)(gi + l);
        S[SW(l)]   = make_float2(vv.x, vv.y);
        S[SW(l|1)] = make_float2(vv.z, vv.w);
    }
    __syncthreads();

    for (int g = tid; g < 512; g += TPB){
        int base = g;
        float2 v[16];
        #pragma unroll
        for (int m = 0; m < 16; m++) v[m] = S[SW(base | (m << 9))];
        set_crx<16,3,2>(v, sCX2[3]);
        set_crx<16,2,1>(v, sCX2[4]);
        set_crx<16,1,0>(v, sCX2[5]);
        #pragma unroll
        for (int m = 0; m < 16; m++) S[SW(base | (m << 9))] = v[m];
    }
    __syncthreads();
    for (int g = tid; g < 512; g += TPB){
        int base = (g & 63) | ((g >> 6) << 10);
        float2 v[16];
        #pragma unroll
        for (int m = 0; m < 16; m++) v[m] = S[SW(base | (m << 6))];
        set_crx<16,3,2>(v, sCX2[6]);
        set_crx<16,2,1>(v, sCX2[7]);
        set_crx<16,1,0>(v, sCX2[8]);
        #pragma unroll
        for (int m = 0; m < 16; m++) S[SW(base | (m << 6))] = v[m];
    }
    __syncthreads();
    for (int g = tid; g < 512; g += TPB){
        int base = (g & 7) | ((g >> 3) << 7);
        float2 v[16];
        #pragma unroll
        for (int m = 0; m < 16; m++) v[m] = S[SW(base | (m << 3))];
        set_crx<16,3,2>(v, sCX2[9]);
        set_crx<16,2,1>(v, sCX2[10]);
        set_crx<16,1,0>(v, sCX2[11]);
        #pragma unroll
        for (int m = 0; m < 16; m++) S[SW(base | (m << 3))] = v[m];
    }
    __syncthreads();
    for (int g = tid; g < 512; g += TPB){
        int base = g << 4;
        float2 v[16];
        #pragma unroll
        for (int m = 0; m < 16; m++) v[m] = S[SW(base | m)];
        set_crx<16,3,2>(v, sCX2[12]);
        set_crx<16,2,1>(v, sCX2[13]);
        set_crx<16,1,0>(v, sCX2[14]);
        #pragma unroll
        for (int m = 0; m < 16; m++) S[SW(base | m)] = v[m];
    }
    __syncthreads();

    float2* go = g_state + b*DIM + (t << 13);
    for (int l = tid*2; l < LOC; l += TPB*2){
        float2 a = S[SW(l)], c2 = S[SW(l|1)];
        *(float4*)(go + l) = make_float4(a.x, a.y, c2.x, c2.y);
    }
}

// ---------------------------------------------------------------------------
// K5: streaming CRX15 (L2) + PauliZ expvals. Pairs (j, j|0x8000), ctrl = bit0.
// ---------------------------------------------------------------------------
__global__ void __launch_bounds__(TPB)
k5_expv(const float* __restrict__ x1){
    __shared__ float sred[8][NQ];
    int tid = threadIdx.x, t = blockIdx.x, b = blockIdx.y;
    float cv = x1[15];
    float c = cosf(0.5f*cv), s = sinf(0.5f*cv);
    const float2* gs = g_state + b*DIM;
    float acc[NQ];
    #pragma unroll
    for (int q = 0; q < NQ; q++) acc[q] = 0.f;
    #pragma unroll 4
    for (int k = 0; k < 16; k++){
        int j = (t << 12) + (k << 8) + tid;     // bit15 = 0
        float2 a0 = gs[j];
        float2 a1 = gs[j + 32768];
        if (j & 1) aprx(a0, a1, c, s);          // ctrl wire15 = bit0
        float p0 = a0.x*a0.x + a0.y*a0.y;
        float p1 = a1.x*a1.x + a1.y*a1.y;
        acc[0] += p0 - p1;                      // wire0: bit15 differs
        float ps = p0 + p1;
        #pragma unroll
        for (int q = 1; q < NQ; q++)
            acc[q] += ((j >> (15 - q)) & 1) ? -ps : ps;
    }
    #pragma unroll
    for (int q = 0; q < NQ; q++){
        float v = acc[q];
        #pragma unroll
        for (int off = 16; off > 0; off >>= 1)
            v += __shfl_down_sync(0xffffffffu, v, off);
        acc[q] = v;
    }
    int w = tid >> 5, lane = tid & 31;
    if (lane == 0){
        #pragma unroll
        for (int q = 0; q < NQ; q++) sred[w][q] = acc[q];
    }
    __syncthreads();
    if (tid < NQ){
        float v = 0.f;
        #pragma unroll
        for (int w2 = 0; w2 < 8; w2++) v += sred[w2][tid];
        atomicAdd(&g_expv[b*NQ + tid], v);
    }
}

__global__ void fc_kernel(const float* __restrict__ fc_w, const float* __restrict__ fc_b,
                          float* __restrict__ out){
    int b = threadIdx.x;
    if (b >= NB) return;
    float f[NQ];
    #pragma unroll
    for (int q = 0; q < NQ; q++) f[q] = g_expv[b*NQ + q];
    float lg[NC];
    float mx = -1e30f;
    #pragma unroll
    for (int c = 0; c < NC; c++){
        float s = fc_b[c];
        #pragma unroll
        for (int q = 0; q < NQ; q++) s = fmaf(fc_w[c*NQ + q], f[q], s);
        lg[c] = s;
        mx = fmaxf(mx, s);
    }
    float se = 0.f;
    #pragma unroll
    for (int c = 0; c < NC; c++) se += expf(lg[c] - mx);
    float ls = logf(se);
    #pragma unroll
    for (int c = 0; c < NC; c++) out[b*NC + c] = lg[c] - mx - ls;
}

extern "C" void kernel_launch(void* const* d_in, const int* in_sizes, int n_in,
                              void* d_out, int out_size){
    const float* x   = (const float*)d_in[0];
    const float* w0  = (const float*)d_in[1];
    const float* x0  = (const float*)d_in[2];
    const float* w1  = (const float*)d_in[3];
    const float* x1  = (const float*)d_in[4];
    const float* fcw = (const float*)d_in[5];
    const float* fcb = (const float*)d_in[6];

    const int smem = LOC * sizeof(float2);   // 64 KB
    cudaFuncSetAttribute(k2_passB1, cudaFuncAttributeMaxDynamicSharedMemorySize, smem);
    cudaFuncSetAttribute(k3_passA2, cudaFuncAttributeMaxDynamicSharedMemorySize, smem);
    cudaFuncSetAttribute(k4_passB2, cudaFuncAttributeMaxDynamicSharedMemorySize, smem);

    dim3 grid(8, NB);
    k1_init <<<grid, TPB>>>(x, w0, x0);
    k2_passB1<<<grid, TPB, smem>>>(x, w0, x0, w1, x1);
    k3_passA2<<<grid, TPB, smem>>>(x, x0, w1, x1);
    k4_passB2<<<grid, TPB, smem>>>(x, w1, x1);
    k5_expv <<<grid, TPB>>>(x1);
    fc_kernel<<<1, 64>>>(fcw, fcb, (float*)d_out);
}

// round 4
// speedup vs baseline: 1.4019x; 1.1874x over previous
#include <cuda_runtime.h>

#define NQ  16
#define DIM 65536
#define NB  64
#define NC  23
#define TPB 256
#define NPAIR 4096   // float4 pairs per 64KB tile

__device__ float2 g_state[NB * DIM];   // 32 MB scratch
__device__ float  g_expv[NB * NQ];

struct P2 { float2 lo, hi; };          // lo: amp bit0=0 (wire15=0), hi: bit0=1

__device__ __forceinline__ float2 cmulf(float2 a, float2 b){
    return make_float2(a.x*b.x - a.y*b.y, a.x*b.y + a.y*b.x);
}
__device__ __forceinline__ void ap1q(float2 &v0, float2 &v1,
                                     float2 u00, float2 u01, float2 u10, float2 u11){
    float2 a = v0, b = v1;
    v0.x = u00.x*a.x - u00.y*a.y + u01.x*b.x - u01.y*b.y;
    v0.y = u00.x*a.y + u00.y*a.x + u01.x*b.y + u01.y*b.x;
    v1.x = u10.x*a.x - u10.y*a.y + u11.x*b.x - u11.y*b.y;
    v1.y = u10.x*a.y + u10.y*a.x + u11.x*b.y + u11.y*b.x;
}
// RX(theta): [[c, -i s], [-i s, c]] with c=cos(t/2), s=sin(t/2)
__device__ __forceinline__ void aprx(float2 &v0, float2 &v1, float c, float s){
    float2 a = v0, b = v1;
    v0 = make_float2(fmaf(c, a.x,  s*b.y), fmaf(c, a.y, -s*b.x));
    v1 = make_float2(fmaf(c, b.x,  s*a.y), fmaf(c, b.y, -s*a.x));
}
// pair-space swizzle: permutes low 3 bits from bits 3..8 -> bank-conflict-free rounds
__device__ __forceinline__ int FP(int p){ return p ^ ((p>>3)&7) ^ ((p>>6)&7); }

__device__ __forceinline__ P2 ld4(const float4* S, int i){
    float4 t = S[i]; P2 r; r.lo = make_float2(t.x,t.y); r.hi = make_float2(t.z,t.w); return r;
}
__device__ __forceinline__ void st4(float4* S, int i, P2 v){
    S[i] = make_float4(v.lo.x, v.lo.y, v.hi.x, v.hi.y);
}

// Fused U = Rot(w[q]) * RX(x[b,q]); CRX params (cos, sin) of half-angle.
__device__ __forceinline__ void setup_one(const float* __restrict__ x,
                                          const float* __restrict__ w,
                                          const float* __restrict__ xc,
                                          int b, int q, float2 (*sU)[4], float2* sCX){
    float xv = x[b*NQ + q];
    float hc = cosf(0.5f*xv), hs = sinf(0.5f*xv);
    float phi = w[q*3+0], th = w[q*3+1], om = w[q*3+2];
    float ct = cosf(0.5f*th), st = sinf(0.5f*th);
    float pp = 0.5f*(phi+om), mm = 0.5f*(phi-om);
    float2 A  = make_float2( cosf(pp)*ct, -sinf(pp)*ct);
    float2 Bm = make_float2(-cosf(mm)*st, -sinf(mm)*st);
    float2 C  = make_float2( cosf(mm)*st, -sinf(mm)*st);
    float2 D  = make_float2( cosf(pp)*ct,  sinf(pp)*ct);
    sU[q][0] = make_float2(A.x*hc + Bm.y*hs,   A.y*hc - Bm.x*hs);
    sU[q][1] = make_float2(A.y*hs + Bm.x*hc,  -A.x*hs + Bm.y*hc);
    sU[q][2] = make_float2(C.x*hc + D.y*hs,    C.y*hc - D.x*hs);
    sU[q][3] = make_float2(C.y*hs + D.x*hc,   -C.x*hs + D.y*hc);
    float cv = xc[q];
    sCX[q] = make_float2(cosf(0.5f*cv), sinf(0.5f*cv));
}

// ---- gate helpers on P2 arrays (gate on external pair-bit K) ----
template<int N, int K>
__device__ __forceinline__ void g1q(P2* v, const float2* u){
    float2 u00 = u[0], u01 = u[1], u10 = u[2], u11 = u[3];
    #pragma unroll
    for (int m = 0; m < N; m++)
        if (!(m & (1 << K))){
            ap1q(v[m].lo, v[m | (1 << K)].lo, u00, u01, u10, u11);
            ap1q(v[m].hi, v[m | (1 << K)].hi, u00, u01, u10, u11);
        }
}
template<int N, int KC, int KT>
__device__ __forceinline__ void gcrx(P2* v, float2 cs){
    #pragma unroll
    for (int m = 0; m < N; m++)
        if ((m & (1 << KC)) && !(m & (1 << KT))){
            aprx(v[m].lo, v[m | (1 << KT)].lo, cs.x, cs.y);
            aprx(v[m].hi, v[m | (1 << KT)].hi, cs.x, cs.y);
        }
}
// 1q on the pair bit (wire15)
template<int N>
__device__ __forceinline__ void g1q_pair(P2* v, const float2* u){
    float2 u00 = u[0], u01 = u[1], u10 = u[2], u11 = u[3];
    #pragma unroll
    for (int m = 0; m < N; m++) ap1q(v[m].lo, v[m].hi, u00, u01, u10, u11);
}
// CRX with ctrl = external bit KC, target = pair bit (CRX14)
template<int N, int KC>
__device__ __forceinline__ void gcrx_tgtpair(P2* v, float2 cs){
    #pragma unroll
    for (int m = 0; m < N; m++)
        if (m & (1 << KC)) aprx(v[m].lo, v[m].hi, cs.x, cs.y);
}
// CRX with ctrl = pair bit (wire15=1 -> .hi), target = external bit KT (CRX15)
template<int N, int KT>
__device__ __forceinline__ void gcrx_ctrlpair(P2* v, float2 cs){
    #pragma unroll
    for (int m = 0; m < N; m++)
        if (!(m & (1 << KT))) aprx(v[m].hi, v[m | (1 << KT)].hi, cs.x, cs.y);
}

// ---------------------------------------------------------------------------
// K1: analytic product state (L1 1q on wires 0..9,12..15; wires 10,11 stay |0>)
//     + CRX0,1,2 (L1). amp i = s | (t<<9) | (m<<12). Pure write kernel.
// ---------------------------------------------------------------------------
__global__ void __launch_bounds__(TPB)
k1_init(const float* __restrict__ x, const float* __restrict__ w0,
        const float* __restrict__ x0){
    __shared__ float2 sU[NQ][4];
    __shared__ float2 sCX[NQ];
    __shared__ float2 Tlo[512];
    __shared__ float2 Thi[16];
    int tid = threadIdx.x, t = blockIdx.x, b = blockIdx.y;
    if (tid < 16) setup_one(x, w0, x0, b, tid, sU, sCX);
    if (t == 0 && tid < NQ) g_expv[b*NQ + tid] = 0.f;   // reset per replay
    __syncthreads();
    for (int s = tid; s < 512; s += TPB){
        float2 a = make_float2(1.f, 0.f);
        #pragma unroll
        for (int k = 0; k < 9; k++){
            int wire = 15 - k;
            int bit  = (s >> k) & 1;
            if (wire == 10 || wire == 11){ if (bit) a = make_float2(0.f, 0.f); }
            else a = cmulf(a, sU[wire][bit ? 2 : 0]);
        }
        Tlo[s] = a;
    }
    if (tid < 16){
        int m = tid;
        float2 a = sU[0][((m >> 3) & 1) ? 2 : 0];
        a = cmulf(a, sU[1][((m >> 2) & 1) ? 2 : 0]);
        a = cmulf(a, sU[2][((m >> 1) & 1) ? 2 : 0]);
        a = cmulf(a, sU[3][( m       & 1) ? 2 : 0]);
        a = cmulf(a, sU[4][((t >> 2) & 1) ? 2 : 0]);
        a = cmulf(a, sU[5][((t >> 1) & 1) ? 2 : 0]);
        a = cmulf(a, sU[6][( t       & 1) ? 2 : 0]);
        Thi[m] = a;
    }
    __syncthreads();
    float2 cs0 = sCX[0], cs1 = sCX[1], cs2 = sCX[2];
    float2* gb = g_state + b*DIM + (t << 9);
    for (int s = tid; s < 512; s += TPB){
        float2 tlo = Tlo[s];
        float2 v[16];
        #pragma unroll
        for (int m = 0; m < 16; m++) v[m] = cmulf(Thi[m], tlo);
        // plain float2 CRX (m bit3=wire0 ... bit0=wire3)
        #pragma unroll
        for (int m = 0; m < 16; m++) if ((m & 8) && !(m & 4)) aprx(v[m], v[m|4], cs0.x, cs0.y);
        #pragma unroll
        for (int m = 0; m < 16; m++) if ((m & 4) && !(m & 2)) aprx(v[m], v[m|2], cs1.x, cs1.y);
        #pragma unroll
        for (int m = 0; m < 16; m++) if ((m & 2) && !(m & 1)) aprx(v[m], v[m|1], cs2.x, cs2.y);
        #pragma unroll
        for (int m = 0; m < 16; m++) gb[s + (m << 12)] = v[m];
    }
}

// ---------------------------------------------------------------------------
// K2: PassB(L1). locals amp {12..0}, fixed {15,14,13}=t. pair p = amp bits 12..1.
//  r0 {p11..8}: CRX3,4,5(L1) + 1q L2 w3,w4,w5
//  r1 {p8..5}:  CRX6,7,8(L1) + 1q L2 w6,w7,w8
//  r2 {p5..2}:  1qL1 w10,w11; CRX9,10,11(L1); 1q L2 w9,w10,w11
//  r3 {p2..0}+pair: CRX12,13(L1), CRX14(L1,in-pair), 1q L2 w12,w13,w14
// ---------------------------------------------------------------------------
__global__ void __launch_bounds__(TPB, 2)
k2_passB1(const float* __restrict__ x, const float* __restrict__ w0,
          const float* __restrict__ x0, const float* __restrict__ w1,
          const float* __restrict__ x1){
    extern __shared__ float4 S[];
    __shared__ float2 sU1[NQ][4], sU2[NQ][4];
    __shared__ float2 sCX1[NQ], sCX2[NQ];
    int tid = threadIdx.x, t = blockIdx.x, b = blockIdx.y;
    if (tid < 16)      setup_one(x, w0, x0, b, tid,      sU1, sCX1);
    else if (tid < 32) setup_one(x, w1, x1, b, tid - 16, sU2, sCX2);
    __syncthreads();

    const float4* gi = (const float4*)(g_state + b*DIM + (t << 13));
    #pragma unroll
    for (int k = 0; k < 16; k++){ int p = tid + (k << 8); S[FP(p)] = gi[p]; }
    __syncthreads();

    // r0: m bit3=p11(w3) bit2=p10(w4) bit1=p9(w5) bit0=p8(w6)
    { P2 v[16]; int base = tid;
      #pragma unroll
      for (int m = 0; m < 16; m++) v[m] = ld4(S, FP(base | (m << 8)));
      gcrx<16,3,2>(v, sCX1[3]); gcrx<16,2,1>(v, sCX1[4]); gcrx<16,1,0>(v, sCX1[5]);
      g1q<16,3>(v, sU2[3]); g1q<16,2>(v, sU2[4]); g1q<16,1>(v, sU2[5]);
      #pragma unroll
      for (int m = 0; m < 16; m++) st4(S, FP(base | (m << 8)), v[m]);
    }
    __syncthreads();
    // r1: m bit3=p8(w6) bit2=p7(w7) bit1=p6(w8) bit0=p5(w9)
    { P2 v[16]; int g = tid; int base = (g & 31) | ((g >> 5) << 9);
      #pragma unroll
      for (int m = 0; m < 16; m++) v[m] = ld4(S, FP(base | (m << 5)));
      gcrx<16,3,2>(v, sCX1[6]); gcrx<16,2,1>(v, sCX1[7]); gcrx<16,1,0>(v, sCX1[8]);
      g1q<16,3>(v, sU2[6]); g1q<16,2>(v, sU2[7]); g1q<16,1>(v, sU2[8]);
      #pragma unroll
      for (int m = 0; m < 16; m++) st4(S, FP(base | (m << 5)), v[m]);
    }
    __syncthreads();
    // r2: m bit3=p5(w9) bit2=p4(w10) bit1=p3(w11) bit0=p2(w12)
    { P2 v[16]; int g = tid;
      int base = (g & 3) | (((g >> 2) & 1) << 8) | (((g >> 3) & 1) << 6)
               | (((g >> 4) & 1) << 7) | ((g >> 5) << 9);
      #pragma unroll
      for (int m = 0; m < 16; m++) v[m] = ld4(S, FP(base | (m << 2)));
      g1q<16,2>(v, sU1[10]); g1q<16,1>(v, sU1[11]);
      gcrx<16,3,2>(v, sCX1[9]); gcrx<16,2,1>(v, sCX1[10]); gcrx<16,1,0>(v, sCX1[11]);
      g1q<16,3>(v, sU2[9]); g1q<16,2>(v, sU2[10]); g1q<16,1>(v, sU2[11]);
      #pragma unroll
      for (int m = 0; m < 16; m++) st4(S, FP(base | (m << 2)), v[m]);
    }
    __syncthreads();
    // r3: m bit2=p2(w12) bit1=p1(w13) bit0=p0(w14); pair = w15
    #pragma unroll
    for (int it = 0; it < 2; it++){
      P2 v[8]; int g = tid + (it << 8); int base = g << 3;
      #pragma unroll
      for (int m = 0; m < 8; m++) v[m] = ld4(S, FP(base | m));
      gcrx<8,2,1>(v, sCX1[12]); gcrx<8,1,0>(v, sCX1[13]); gcrx_tgtpair<8,0>(v, sCX1[14]);
      g1q<8,2>(v, sU2[12]); g1q<8,1>(v, sU2[13]); g1q<8,0>(v, sU2[14]);
      #pragma unroll
      for (int m = 0; m < 8; m++) st4(S, FP(base | m), v[m]);
    }
    __syncthreads();

    float4* go = (float4*)(g_state + b*DIM + (t << 13));
    #pragma unroll
    for (int k = 0; k < 16; k++){ int p = tid + (k << 8); go[p] = S[FP(p)]; }
}

// ---------------------------------------------------------------------------
// K3: PassA(L2). locals amp {15..12, 8..0}, fixed {11,10,9}=t.
//     pair p: bits 0..7 = amp 1..8; bits 8..11 = amp 12..15.
//     ONE round over m = p{11..8} + pair:
//       CRX15(L1): ctrl pair(.hi), tgt p11(w0)
//       1q L2 w15(pair), w0(m3), w1(m2), w2(m1); CRX0(3,2), CRX1(2,1), CRX2(1,0)
// ---------------------------------------------------------------------------
__global__ void __launch_bounds__(TPB, 2)
k3_passA2(const float* __restrict__ x, const float* __restrict__ x0,
          const float* __restrict__ w1, const float* __restrict__ x1){
    extern __shared__ float4 S[];
    __shared__ float2 sU2[NQ][4], sCX2[NQ];
    __shared__ float2 c15s;
    int tid = threadIdx.x, t = blockIdx.x, b = blockIdx.y;
    if (tid < 16) setup_one(x, w1, x1, b, tid, sU2, sCX2);
    else if (tid == 16){
        float cv = x0[15];
        c15s = make_float2(cosf(0.5f*cv), sinf(0.5f*cv));
    }
    __syncthreads();

    const float4* g4 = (const float4*)(g_state + b*DIM);
    #pragma unroll
    for (int k = 0; k < 16; k++){
        int p = tid + (k << 8);
        int gi = (p & 255) | (t << 8) | ((p >> 8) << 11);
        S[FP(p)] = g4[gi];
    }
    __syncthreads();

    { P2 v[16]; int base = tid;
      #pragma unroll
      for (int m = 0; m < 16; m++) v[m] = ld4(S, FP(base | (m << 8)));
      float2 c15 = c15s;
      gcrx_ctrlpair<16,3>(v, c15);      // CRX15 (L1): w15 -> w0
      g1q_pair<16>(v, sU2[15]);
      g1q<16,3>(v, sU2[0]); g1q<16,2>(v, sU2[1]); g1q<16,1>(v, sU2[2]);
      gcrx<16,3,2>(v, sCX2[0]); gcrx<16,2,1>(v, sCX2[1]); gcrx<16,1,0>(v, sCX2[2]);
      #pragma unroll
      for (int m = 0; m < 16; m++) st4(S, FP(base | (m << 8)), v[m]);
    }
    __syncthreads();

    float4* go = (float4*)(g_state + b*DIM);
    #pragma unroll
    for (int k = 0; k < 16; k++){
        int p = tid + (k << 8);
        int gi = (p & 255) | (t << 8) | ((p >> 8) << 11);
        go[gi] = S[FP(p)];
    }
}

// ---------------------------------------------------------------------------
// K4: PassB(L2). Same layout/rounds as K2, gates CRX3..14 (L2) only.
// ---------------------------------------------------------------------------
__global__ void __launch_bounds__(TPB, 2)
k4_passB2(const float* __restrict__ x, const float* __restrict__ w1,
          const float* __restrict__ x1){
    extern __shared__ float4 S[];
    __shared__ float2 sU2[NQ][4], sCX2[NQ];
    int tid = threadIdx.x, t = blockIdx.x, b = blockIdx.y;
    if (tid < 16) setup_one(x, w1, x1, b, tid, sU2, sCX2);
    __syncthreads();

    const float4* gi = (const float4*)(g_state + b*DIM + (t << 13));
    #pragma unroll
    for (int k = 0; k < 16; k++){ int p = tid + (k << 8); S[FP(p)] = gi[p]; }
    __syncthreads();

    { P2 v[16]; int base = tid;
      #pragma unroll
      for (int m = 0; m < 16; m++) v[m] = ld4(S, FP(base | (m << 8)));
      gcrx<16,3,2>(v, sCX2[3]); gcrx<16,2,1>(v, sCX2[4]); gcrx<16,1,0>(v, sCX2[5]);
      #pragma unroll
      for (int m = 0; m < 16; m++) st4(S, FP(base | (m << 8)), v[m]);
    }
    __syncthreads();
    { P2 v[16]; int g = tid; int base = (g & 31) | ((g >> 5) << 9);
      #pragma unroll
      for (int m = 0; m < 16; m++) v[m] = ld4(S, FP(base | (m << 5)));
      gcrx<16,3,2>(v, sCX2[6]); gcrx<16,2,1>(v, sCX2[7]); gcrx<16,1,0>(v, sCX2[8]);
      #pragma unroll
      for (int m = 0; m < 16; m++) st4(S, FP(base | (m << 5)), v[m]);
    }
    __syncthreads();
    { P2 v[16]; int g = tid;
      int base = (g & 3) | (((g >> 2) & 1) << 8) | (((g >> 3) & 1) << 6)
               | (((g >> 4) & 1) << 7) | ((g >> 5) << 9);
      #pragma unroll
      for (int m = 0; m < 16; m++) v[m] = ld4(S, FP(base | (m << 2)));
      gcrx<16,3,2>(v, sCX2[9]); gcrx<16,2,1>(v, sCX2[10]); gcrx<16,1,0>(v, sCX2[11]);
      #pragma unroll
      for (int m = 0; m < 16; m++) st4(S, FP(base | (m << 2)), v[m]);
    }
    __syncthreads();
    #pragma unroll
    for (int it = 0; it < 2; it++){
      P2 v[8]; int g = tid + (it << 8); int base = g << 3;
      #pragma unroll
      for (int m = 0; m < 8; m++) v[m] = ld4(S, FP(base | m));
      gcrx<8,2,1>(v, sCX2[12]); gcrx<8,1,0>(v, sCX2[13]); gcrx_tgtpair<8,0>(v, sCX2[14]);
      #pragma unroll
      for (int m = 0; m < 8; m++) st4(S, FP(base | m), v[m]);
    }
    __syncthreads();

    float4* go = (float4*)(g_state + b*DIM + (t << 13));
    #pragma unroll
    for (int k = 0; k < 16; k++){ int p = tid + (k << 8); go[p] = S[FP(p)]; }
}

// ---------------------------------------------------------------------------
// K5: streaming CRX15 (L2) + PauliZ expvals, float4 loads.
//     pair pr (bit15=0) partners pr+16384; ctrl wire15 = odd amps (.hi).
// ---------------------------------------------------------------------------
__global__ void __launch_bounds__(TPB)
k5_expv(const float* __restrict__ x1){
    __shared__ float sred[8][NQ];
    int tid = threadIdx.x, t = blockIdx.x, b = blockIdx.y;
    float cv = x1[15];
    float c = cosf(0.5f*cv), s = sinf(0.5f*cv);
    const float4* g4 = (const float4*)(g_state + b*DIM);
    float acc[NQ];
    #pragma unroll
    for (int q = 0; q < NQ; q++) acc[q] = 0.f;
    #pragma unroll
    for (int k = 0; k < 8; k++){
        int pr = (t << 11) + (k << 8) + tid;     // low half pair index
        float4 A = g4[pr];
        float4 B = g4[pr + 16384];
        float2 a1 = make_float2(A.z, A.w), b1 = make_float2(B.z, B.w);
        aprx(a1, b1, c, s);                      // CRX15(L2): odd amps, tgt bit15
        float pA0 = A.x*A.x + A.y*A.y, pA1 = a1.x*a1.x + a1.y*a1.y;
        float pB0 = B.x*B.x + B.y*B.y, pB1 = b1.x*b1.x + b1.y*b1.y;
        int i0 = pr << 1;                         // amp index, bit0=0
        acc[0]  += (pA0 + pA1) - (pB0 + pB1);     // wire0  = bit15
        acc[15] += (pA0 - pA1) + (pB0 - pB1);     // wire15 = bit0
        float ps = pA0 + pA1 + pB0 + pB1;
        #pragma unroll
        for (int q = 1; q < 15; q++)
            acc[q] += ((i0 >> (15 - q)) & 1) ? -ps : ps;
    }
    #pragma unroll
    for (int q = 0; q < NQ; q++){
        float v = acc[q];
        #pragma unroll
        for (int off = 16; off > 0; off >>= 1)
            v += __shfl_down_sync(0xffffffffu, v, off);
        acc[q] = v;
    }
    int w = tid >> 5, lane = tid & 31;
    if (lane == 0){
        #pragma unroll
        for (int q = 0; q < NQ; q++) sred[w][q] = acc[q];
    }
    __syncthreads();
    if (tid < NQ){
        float v = 0.f;
        #pragma unroll
        for (int w2 = 0; w2 < 8; w2++) v += sred[w2][tid];
        atomicAdd(&g_expv[b*NQ + tid], v);
    }
}

__global__ void fc_kernel(const float* __restrict__ fc_w, const float* __restrict__ fc_b,
                          float* __restrict__ out){
    int b = threadIdx.x;
    if (b >= NB) return;
    float f[NQ];
    #pragma unroll
    for (int q = 0; q < NQ; q++) f[q] = g_expv[b*NQ + q];
    float lg[NC];
    float mx = -1e30f;
    #pragma unroll
    for (int c = 0; c < NC; c++){
        float s = fc_b[c];
        #pragma unroll
        for (int q = 0; q < NQ; q++) s = fmaf(fc_w[c*NQ + q], f[q], s);
        lg[c] = s;
        mx = fmaxf(mx, s);
    }
    float se = 0.f;
    #pragma unroll
    for (int c = 0; c < NC; c++) se += expf(lg[c] - mx);
    float ls = logf(se);
    #pragma unroll
    for (int c = 0; c < NC; c++) out[b*NC + c] = lg[c] - mx - ls;
}

extern "C" void kernel_launch(void* const* d_in, const int* in_sizes, int n_in,
                              void* d_out, int out_size){
    const float* x   = (const float*)d_in[0];
    const float* w0  = (const float*)d_in[1];
    const float* x0  = (const float*)d_in[2];
    const float* w1  = (const float*)d_in[3];
    const float* x1  = (const float*)d_in[4];
    const float* fcw = (const float*)d_in[5];
    const float* fcb = (const float*)d_in[6];

    const int smem = NPAIR * sizeof(float4);   // 64 KB
    cudaFuncSetAttribute(k2_passB1, cudaFuncAttributeMaxDynamicSharedMemorySize, smem);
    cudaFuncSetAttribute(k3_passA2, cudaFuncAttributeMaxDynamicSharedMemorySize, smem);
    cudaFuncSetAttribute(k4_passB2, cudaFuncAttributeMaxDynamicSharedMemorySize, smem);

    dim3 grid(8, NB);
    k1_init  <<<grid, TPB>>>(x, w0, x0);
    k2_passB1<<<grid, TPB, smem>>>(x, w0, x0, w1, x1);
    k3_passA2<<<grid, TPB, smem>>>(x, x0, w1, x1);
    k4_passB2<<<grid, TPB, smem>>>(x, w1, x1);
    k5_expv  <<<grid, TPB>>>(x1);
    fc_kernel<<<1, 64>>>(fcw, fcb, (float*)d_out);
}

// round 5
// speedup vs baseline: 1.4071x; 1.0037x over previous
#include <cuda_runtime.h>

#define NQ  16
#define DIM 65536
#define NB  64
#define NC  23
#define TPB 256
#define NPAIR 4096   // float4 pairs per 64KB tile

__device__ float2 g_state[NB * DIM];   // 32 MB scratch
__device__ float  g_expv[NB * NQ];

struct P2 { float2 lo, hi; };          // lo: amp bit0=0 (wire15=0), hi: bit0=1

__device__ __forceinline__ float2 cmulf(float2 a, float2 b){
    return make_float2(a.x*b.x - a.y*b.y, a.x*b.y + a.y*b.x);
}
__device__ __forceinline__ void ap1q(float2 &v0, float2 &v1,
                                     float2 u00, float2 u01, float2 u10, float2 u11){
    float2 a = v0, b = v1;
    v0.x = u00.x*a.x - u00.y*a.y + u01.x*b.x - u01.y*b.y;
    v0.y = u00.x*a.y + u00.y*a.x + u01.x*b.y + u01.y*b.x;
    v1.x = u10.x*a.x - u10.y*a.y + u11.x*b.x - u11.y*b.y;
    v1.y = u10.x*a.y + u10.y*a.x + u11.x*b.y + u11.y*b.x;
}
// RX(theta): [[c, -i s], [-i s, c]] with c=cos(t/2), s=sin(t/2)
__device__ __forceinline__ void aprx(float2 &v0, float2 &v1, float c, float s){
    float2 a = v0, b = v1;
    v0 = make_float2(fmaf(c, a.x,  s*b.y), fmaf(c, a.y, -s*b.x));
    v1 = make_float2(fmaf(c, b.x,  s*a.y), fmaf(c, b.y, -s*a.x));
}
// pair-space swizzle: low-3-bit permutation keyed by bits 3..8 -> conflict-free rounds
__device__ __forceinline__ int FP(int p){ return p ^ ((p>>3)&7) ^ ((p>>6)&7); }

__device__ __forceinline__ P2 ld4(const float4* S, int i){
    float4 t = S[i]; P2 r; r.lo = make_float2(t.x,t.y); r.hi = make_float2(t.z,t.w); return r;
}
__device__ __forceinline__ void st4(float4* S, int i, P2 v){
    S[i] = make_float4(v.lo.x, v.lo.y, v.hi.x, v.hi.y);
}

// Fused U = Rot(w[q]) * RX(x[b,q]); CRX params (cos, sin) of half-angle.
__device__ __forceinline__ void setup_one(const float* __restrict__ x,
                                          const float* __restrict__ w,
                                          const float* __restrict__ xc,
                                          int b, int q, float2 (*sU)[4], float2* sCX){
    float xv = x[b*NQ + q];
    float hc = cosf(0.5f*xv), hs = sinf(0.5f*xv);
    float phi = w[q*3+0], th = w[q*3+1], om = w[q*3+2];
    float ct = cosf(0.5f*th), st = sinf(0.5f*th);
    float pp = 0.5f*(phi+om), mm = 0.5f*(phi-om);
    float2 A  = make_float2( cosf(pp)*ct, -sinf(pp)*ct);
    float2 Bm = make_float2(-cosf(mm)*st, -sinf(mm)*st);
    float2 C  = make_float2( cosf(mm)*st, -sinf(mm)*st);
    float2 D  = make_float2( cosf(pp)*ct,  sinf(pp)*ct);
    sU[q][0] = make_float2(A.x*hc + Bm.y*hs,   A.y*hc - Bm.x*hs);
    sU[q][1] = make_float2(A.y*hs + Bm.x*hc,  -A.x*hs + Bm.y*hc);
    sU[q][2] = make_float2(C.x*hc + D.y*hs,    C.y*hc - D.x*hs);
    sU[q][3] = make_float2(C.y*hs + D.x*hc,   -C.x*hs + D.y*hc);
    float cv = xc[q];
    sCX[q] = make_float2(cosf(0.5f*cv), sinf(0.5f*cv));
}

// ---- gate helpers on P2 arrays ----
template<int N, int K>
__device__ __forceinline__ void g1q(P2* v, const float2* u){
    float2 u00 = u[0], u01 = u[1], u10 = u[2], u11 = u[3];
    #pragma unroll
    for (int m = 0; m < N; m++)
        if (!(m & (1 << K))){
            ap1q(v[m].lo, v[m | (1 << K)].lo, u00, u01, u10, u11);
            ap1q(v[m].hi, v[m | (1 << K)].hi, u00, u01, u10, u11);
        }
}
template<int N, int KC, int KT>
__device__ __forceinline__ void gcrx(P2* v, float2 cs){
    #pragma unroll
    for (int m = 0; m < N; m++)
        if ((m & (1 << KC)) && !(m & (1 << KT))){
            aprx(v[m].lo, v[m | (1 << KT)].lo, cs.x, cs.y);
            aprx(v[m].hi, v[m | (1 << KT)].hi, cs.x, cs.y);
        }
}
template<int N>
__device__ __forceinline__ void g1q_pair(P2* v, const float2* u){
    float2 u00 = u[0], u01 = u[1], u10 = u[2], u11 = u[3];
    #pragma unroll
    for (int m = 0; m < N; m++) ap1q(v[m].lo, v[m].hi, u00, u01, u10, u11);
}
// CRX ctrl = external bit KC, target = pair bit
template<int N, int KC>
__device__ __forceinline__ void gcrx_tgtpair(P2* v, float2 cs){
    #pragma unroll
    for (int m = 0; m < N; m++)
        if (m & (1 << KC)) aprx(v[m].lo, v[m].hi, cs.x, cs.y);
}
// CRX ctrl = pair bit (hi half), target = external bit KT
template<int N, int KT>
__device__ __forceinline__ void gcrx_ctrlpair(P2* v, float2 cs){
    #pragma unroll
    for (int m = 0; m < N; m++)
        if (!(m & (1 << KT))) aprx(v[m].hi, v[m | (1 << KT)].hi, cs.x, cs.y);
}

// ---------------------------------------------------------------------------
// K2: analytic init (product + CRX0,1,2 L1) + PassB(L1) + cross-layer L2 1q.
// Tile: t = amp bits 15..13, locals 12..0.  pair p = amp bits 12..1.
// Rounds (ext pair bits, m2>m1>m0):
//  r0 {11,10,9}: CRX3,4(L1) + w3,w4(L2)      r1 {9,8,7}: CRX5,6 + w5,w6
//  r2 {7,6,5}:   CRX7,8 + w7,w8              r3 {5,4,3}: w10,w11(L1); CRX9,10; w9,w10(L2)
//  r4 {3,2,1}:   CRX11,12 + w11,w12(L2)      r5 {1,0}+pair: CRX13,14(L1) + w13,w14(L2)
// ---------------------------------------------------------------------------
__global__ void __launch_bounds__(TPB, 3)
k2_initB1(const float* __restrict__ x, const float* __restrict__ w0,
          const float* __restrict__ x0, const float* __restrict__ w1,
          const float* __restrict__ x1){
    extern __shared__ float4 S[];
    __shared__ float2 sU1[NQ][4], sU2[NQ][4];
    __shared__ float2 sCX1[NQ], sCX2[NQ];
    __shared__ float2 sT4[16];
    __shared__ float2 sT3[8];
    __shared__ float2 sTlo[512];
    int tid = threadIdx.x, t = blockIdx.x, b = blockIdx.y;
    if (tid < 16)      setup_one(x, w0, x0, b, tid,      sU1, sCX1);
    else if (tid < 32) setup_one(x, w1, x1, b, tid - 16, sU2, sCX2);
    if (t == 0 && tid >= 32 && tid < 48) g_expv[b*NQ + (tid-32)] = 0.f;  // replay reset
    __syncthreads();

    // Tlo over amp bits 8..0 (wires 15..7); wires 10,11 (amp bits 5,4) stay |0>
    for (int s9 = tid; s9 < 512; s9 += TPB){
        float2 a = make_float2(1.f, 0.f);
        #pragma unroll
        for (int k = 0; k < 9; k++){
            int wire = 15 - k;
            int bit  = (s9 >> k) & 1;
            if (wire == 10 || wire == 11){ if (bit) a = make_float2(0.f, 0.f); }
            else a = cmulf(a, sU1[wire][bit ? 2 : 0]);
        }
        sTlo[s9] = a;
    }
    // T3 over amp bits 11..9 (wires 4,5,6)
    if (tid >= 48 && tid < 56){
        int j = tid - 48;
        float2 a = cmulf(sU1[4][(j>>2)&1 ? 2 : 0], sU1[5][(j>>1)&1 ? 2 : 0]);
        sT3[j] = cmulf(a, sU1[6][j&1 ? 2 : 0]);
    }
    // T4 product over amp bits 15..12 (wires 0..3): m bit3=w0 .. bit0=w3
    if (tid >= 64 && tid < 80){
        int m = tid - 64;
        float2 a = cmulf(sU1[0][(m>>3)&1 ? 2 : 0], sU1[1][(m>>2)&1 ? 2 : 0]);
        a = cmulf(a, sU1[2][(m>>1)&1 ? 2 : 0]);
        sT4[m] = cmulf(a, sU1[3][m&1 ? 2 : 0]);
    }
    __syncthreads();
    // CRX0,1,2 (L1) on the 16-vector sT4
    if (tid < 4){ float2 cs = sCX1[0]; aprx(sT4[8+tid], sT4[12+tid], cs.x, cs.y); }
    __syncthreads();
    if (tid < 4){ float2 cs = sCX1[1]; int m = (tid&1) | ((tid>>1)<<3) | 4;
                  aprx(sT4[m], sT4[m|2], cs.x, cs.y); }
    __syncthreads();
    if (tid < 4){ float2 cs = sCX1[2]; int m = 2 + 4*tid;
                  aprx(sT4[m], sT4[m|1], cs.x, cs.y); }
    __syncthreads();

    // Fill tile analytically: amp i = (p<<1|b0) | (t<<13)
    #pragma unroll
    for (int k = 0; k < 16; k++){
        int p = tid + (k << 8);
        float2 c = cmulf(sT4[(t<<1) | (k>>3)], sT3[k & 7]);
        float4 tl = ((const float4*)sTlo)[p & 255];
        P2 v;
        v.lo = cmulf(c, make_float2(tl.x, tl.y));
        v.hi = cmulf(c, make_float2(tl.z, tl.w));
        st4(S, FP(p), v);
    }
    __syncthreads();

    // r0: m2=p11(w3) m1=p10(w4) m0=p9(w5)
    #pragma unroll
    for (int it = 0; it < 2; it++){
      P2 v[8]; int g = tid + (it<<8); int base = g;                 // free p0..p8
      #pragma unroll
      for (int m = 0; m < 8; m++) v[m] = ld4(S, FP(base | (m << 9)));
      gcrx<8,2,1>(v, sCX1[3]); gcrx<8,1,0>(v, sCX1[4]);
      g1q<8,2>(v, sU2[3]); g1q<8,1>(v, sU2[4]);
      #pragma unroll
      for (int m = 0; m < 8; m++) st4(S, FP(base | (m << 9)), v[m]);
    }
    __syncthreads();
    // r1: m2=p9(w5) m1=p8(w6) m0=p7(w7)
    #pragma unroll
    for (int it = 0; it < 2; it++){
      P2 v[8]; int g = tid + (it<<8); int base = (g & 127) | ((g >> 7) << 10);
      #pragma unroll
      for (int m = 0; m < 8; m++) v[m] = ld4(S, FP(base | (m << 7)));
      gcrx<8,2,1>(v, sCX1[5]); gcrx<8,1,0>(v, sCX1[6]);
      g1q<8,2>(v, sU2[5]); g1q<8,1>(v, sU2[6]);
      #pragma unroll
      for (int m = 0; m < 8; m++) st4(S, FP(base | (m << 7)), v[m]);
    }
    __syncthreads();
    // r2: m2=p7(w7) m1=p6(w8) m0=p5(w9)
    #pragma unroll
    for (int it = 0; it < 2; it++){
      P2 v[8]; int g = tid + (it<<8); int base = (g & 31) | ((g >> 5) << 8);
      #pragma unroll
      for (int m = 0; m < 8; m++) v[m] = ld4(S, FP(base | (m << 5)));
      gcrx<8,2,1>(v, sCX1[7]); gcrx<8,1,0>(v, sCX1[8]);
      g1q<8,2>(v, sU2[7]); g1q<8,1>(v, sU2[8]);
      #pragma unroll
      for (int m = 0; m < 8; m++) st4(S, FP(base | (m << 5)), v[m]);
    }
    __syncthreads();
    // r3: m2=p5(w9) m1=p4(w10) m0=p3(w11)
    #pragma unroll
    for (int it = 0; it < 2; it++){
      P2 v[8]; int g = tid + (it<<8); int base = (g & 7) | ((g >> 3) << 6);
      #pragma unroll
      for (int m = 0; m < 8; m++) v[m] = ld4(S, FP(base | (m << 3)));
      g1q<8,1>(v, sU1[10]); g1q<8,0>(v, sU1[11]);
      gcrx<8,2,1>(v, sCX1[9]); gcrx<8,1,0>(v, sCX1[10]);
      g1q<8,2>(v, sU2[9]); g1q<8,1>(v, sU2[10]);
      #pragma unroll
      for (int m = 0; m < 8; m++) st4(S, FP(base | (m << 3)), v[m]);
    }
    __syncthreads();
    // r4: m2=p3(w11) m1=p2(w12) m0=p1(w13)
    #pragma unroll
    for (int it = 0; it < 2; it++){
      P2 v[8]; int g = tid + (it<<8); int base = (g & 1) | ((g >> 1) << 4);
      #pragma unroll
      for (int m = 0; m < 8; m++) v[m] = ld4(S, FP(base | (m << 1)));
      gcrx<8,2,1>(v, sCX1[11]); gcrx<8,1,0>(v, sCX1[12]);
      g1q<8,2>(v, sU2[11]); g1q<8,1>(v, sU2[12]);
      #pragma unroll
      for (int m = 0; m < 8; m++) st4(S, FP(base | (m << 1)), v[m]);
    }
    __syncthreads();
    // r5: m1=p1(w13) m0=p0(w14), pair=w15
    #pragma unroll
    for (int it = 0; it < 4; it++){
      P2 v[4]; int g = tid + (it<<8); int base = g << 2;
      #pragma unroll
      for (int m = 0; m < 4; m++) v[m] = ld4(S, FP(base | m));
      gcrx<4,1,0>(v, sCX1[13]); gcrx_tgtpair<4,0>(v, sCX1[14]);
      g1q<4,1>(v, sU2[13]); g1q<4,0>(v, sU2[14]);
      #pragma unroll
      for (int m = 0; m < 4; m++) st4(S, FP(base | m), v[m]);
    }
    __syncthreads();

    float4* go = (float4*)(g_state + b*DIM + (t << 13));
    #pragma unroll
    for (int k = 0; k < 16; k++){ int p = tid + (k << 8); go[p] = S[FP(p)]; }
}

// ---------------------------------------------------------------------------
// K3: PassA(L2). Tile: t = amp bits 11..9, locals {15..12, 8..0}.
// p bits: p0..p7 = amp 1..8; p8..p11 = amp 12..15; pair = amp 0.
// ra (v[4], m1=p11(w0) m0=p10(w1) + pair(w15)): CRX15(L1); w15,w0,w1(L2); CRX0(L2)
// rb (v[8], m2=p10(w1) m1=p9(w2) m0=p8(w3)):     w2(L2); CRX1,2(L2)
// ---------------------------------------------------------------------------
__global__ void __launch_bounds__(TPB, 3)
k3_passA2(const float* __restrict__ x, const float* __restrict__ x0,
          const float* __restrict__ w1, const float* __restrict__ x1){
    extern __shared__ float4 S[];
    __shared__ float2 sU2[NQ][4], sCX2[NQ];
    __shared__ float2 c15s;
    int tid = threadIdx.x, t = blockIdx.x, b = blockIdx.y;
    if (tid < 16) setup_one(x, w1, x1, b, tid, sU2, sCX2);
    else if (tid == 16){
        float cv = x0[15];
        c15s = make_float2(cosf(0.5f*cv), sinf(0.5f*cv));
    }
    __syncthreads();

    const float4* g4 = (const float4*)(g_state + b*DIM);
    #pragma unroll
    for (int k = 0; k < 16; k++){
        int p = tid + (k << 8);
        int gi = (p & 255) | (t << 8) | ((p >> 8) << 11);
        S[FP(p)] = g4[gi];
    }
    __syncthreads();

    // ra
    {
      float2 c15 = c15s;
      #pragma unroll
      for (int it = 0; it < 4; it++){
        P2 v[4]; int g = tid + (it<<8); int base = g;               // free p0..p9
        #pragma unroll
        for (int m = 0; m < 4; m++) v[m] = ld4(S, FP(base | (m << 10)));
        gcrx_ctrlpair<4,1>(v, c15);        // CRX15(L1): w15 -> w0 (amp15 = m1)
        g1q_pair<4>(v, sU2[15]);
        g1q<4,1>(v, sU2[0]);
        g1q<4,0>(v, sU2[1]);
        gcrx<4,1,0>(v, sCX2[0]);           // CRX0(L2): w0 -> w1
        #pragma unroll
        for (int m = 0; m < 4; m++) st4(S, FP(base | (m << 10)), v[m]);
      }
    }
    __syncthreads();
    // rb
    #pragma unroll
    for (int it = 0; it < 2; it++){
      P2 v[8]; int g = tid + (it<<8); int base = (g & 255) | ((g >> 8) << 11);
      #pragma unroll
      for (int m = 0; m < 8; m++) v[m] = ld4(S, FP(base | (m << 8)));
      g1q<8,1>(v, sU2[2]);                 // w2(L2)
      gcrx<8,2,1>(v, sCX2[1]);             // CRX1(L2): w1 -> w2
      gcrx<8,1,0>(v, sCX2[2]);             // CRX2(L2): w2 -> w3
      #pragma unroll
      for (int m = 0; m < 8; m++) st4(S, FP(base | (m << 8)), v[m]);
    }
    __syncthreads();

    float4* go = (float4*)(g_state + b*DIM);
    #pragma unroll
    for (int k = 0; k < 16; k++){
        int p = tid + (k << 8);
        int gi = (p & 255) | (t << 8) | ((p >> 8) << 11);
        go[gi] = S[FP(p)];
    }
}

// ---------------------------------------------------------------------------
// K4: PassB(L2): CRX3..13 only (CRX14 moved to K5). Same tiling as K2.
// ---------------------------------------------------------------------------
__global__ void __launch_bounds__(TPB, 3)
k4_passB2(const float* __restrict__ x, const float* __restrict__ w1,
          const float* __restrict__ x1){
    extern __shared__ float4 S[];
    __shared__ float2 sU2[NQ][4], sCX2[NQ];
    int tid = threadIdx.x, t = blockIdx.x, b = blockIdx.y;
    if (tid < 16) setup_one(x, w1, x1, b, tid, sU2, sCX2);
    __syncthreads();

    const float4* gi4 = (const float4*)(g_state + b*DIM + (t << 13));
    #pragma unroll
    for (int k = 0; k < 16; k++){ int p = tid + (k << 8); S[FP(p)] = gi4[p]; }
    __syncthreads();

    // r0 {11,10,9}: CRX3,4
    #pragma unroll
    for (int it = 0; it < 2; it++){
      P2 v[8]; int g = tid + (it<<8); int base = g;
      #pragma unroll
      for (int m = 0; m < 8; m++) v[m] = ld4(S, FP(base | (m << 9)));
      gcrx<8,2,1>(v, sCX2[3]); gcrx<8,1,0>(v, sCX2[4]);
      #pragma unroll
      for (int m = 0; m < 8; m++) st4(S, FP(base | (m << 9)), v[m]);
    }
    __syncthreads();
    // r1 {9,8,7}: CRX5,6
    #pragma unroll
    for (int it = 0; it < 2; it++){
      P2 v[8]; int g = tid + (it<<8); int base = (g & 127) | ((g >> 7) << 10);
      #pragma unroll
      for (int m = 0; m < 8; m++) v[m] = ld4(S, FP(base | (m << 7)));
      gcrx<8,2,1>(v, sCX2[5]); gcrx<8,1,0>(v, sCX2[6]);
      #pragma unroll
      for (int m = 0; m < 8; m++) st4(S, FP(base | (m << 7)), v[m]);
    }
    __syncthreads();
    // r2 {7,6,5}: CRX7,8
    #pragma unroll
    for (int it = 0; it < 2; it++){
      P2 v[8]; int g = tid + (it<<8); int base = (g & 31) | ((g >> 5) << 8);
      #pragma unroll
      for (int m = 0; m < 8; m++) v[m] = ld4(S, FP(base | (m << 5)));
      gcrx<8,2,1>(v, sCX2[7]); gcrx<8,1,0>(v, sCX2[8]);
      #pragma unroll
      for (int m = 0; m < 8; m++) st4(S, FP(base | (m << 5)), v[m]);
    }
    __syncthreads();
    // r3 {5,4,3}: CRX9,10
    #pragma unroll
    for (int it = 0; it < 2; it++){
      P2 v[8]; int g = tid + (it<<8); int base = (g & 7) | ((g >> 3) << 6);
      #pragma unroll
      for (int m = 0; m < 8; m++) v[m] = ld4(S, FP(base | (m << 3)));
      gcrx<8,2,1>(v, sCX2[9]); gcrx<8,1,0>(v, sCX2[10]);
      #pragma unroll
      for (int m = 0; m < 8; m++) st4(S, FP(base | (m << 3)), v[m]);
    }
    __syncthreads();
    // r4 {3,2,1}: CRX11,12
    #pragma unroll
    for (int it = 0; it < 2; it++){
      P2 v[8]; int g = tid + (it<<8); int base = (g & 1) | ((g >> 1) << 4);
      #pragma unroll
      for (int m = 0; m < 8; m++) v[m] = ld4(S, FP(base | (m << 1)));
      gcrx<8,2,1>(v, sCX2[11]); gcrx<8,1,0>(v, sCX2[12]);
      #pragma unroll
      for (int m = 0; m < 8; m++) st4(S, FP(base | (m << 1)), v[m]);
    }
    __syncthreads();
    // r5 {1,0}: CRX13
    #pragma unroll
    for (int it = 0; it < 4; it++){
      P2 v[4]; int g = tid + (it<<8); int base = g << 2;
      #pragma unroll
      for (int m = 0; m < 4; m++) v[m] = ld4(S, FP(base | m));
      gcrx<4,1,0>(v, sCX2[13]);
      #pragma unroll
      for (int m = 0; m < 4; m++) st4(S, FP(base | m), v[m]);
    }
    __syncthreads();

    float4* go = (float4*)(g_state + b*DIM + (t << 13));
    #pragma unroll
    for (int k = 0; k < 16; k++){ int p = tid + (k << 8); go[p] = S[FP(p)]; }
}

// ---------------------------------------------------------------------------
// K5: streaming CRX14(L2) + CRX15(L2) + PauliZ expvals.
// CRX14: ctrl amp bit1 (= pr&1), tgt bit0 -> inside one float4.
// CRX15: ctrl bit0 (hi), tgt bit15 -> pairs (pr, pr+16384).
// ---------------------------------------------------------------------------
__global__ void __launch_bounds__(TPB)
k5_expv(const float* __restrict__ x1){
    __shared__ float sred[8][NQ];
    int tid = threadIdx.x, t = blockIdx.x, b = blockIdx.y;
    float cv15 = x1[15], cv14 = x1[14];
    float c = cosf(0.5f*cv15), s = sinf(0.5f*cv15);
    float c14 = cosf(0.5f*cv14), s14 = sinf(0.5f*cv14);
    const float4* g4 = (const float4*)(g_state + b*DIM);
    float acc[NQ];
    #pragma unroll
    for (int q = 0; q < NQ; q++) acc[q] = 0.f;
    #pragma unroll
    for (int k = 0; k < 8; k++){
        int pr = (t << 11) + (k << 8) + tid;     // low half pair index (bit15=0)
        float4 A = g4[pr];
        float4 B = g4[pr + 16384];
        float2 a0 = make_float2(A.x, A.y), a1 = make_float2(A.z, A.w);
        float2 b0 = make_float2(B.x, B.y), b1 = make_float2(B.z, B.w);
        if (pr & 1){                              // CRX14(L2): amp bit1=1
            aprx(a0, a1, c14, s14);
            aprx(b0, b1, c14, s14);
        }
        aprx(a1, b1, c, s);                       // CRX15(L2): ctrl bit0, tgt bit15
        float pA0 = a0.x*a0.x + a0.y*a0.y, pA1 = a1.x*a1.x + a1.y*a1.y;
        float pB0 = b0.x*b0.x + b0.y*b0.y, pB1 = b1.x*b1.x + b1.y*b1.y;
        int i0 = pr << 1;
        acc[0]  += (pA0 + pA1) - (pB0 + pB1);     // wire0  = bit15
        acc[15] += (pA0 - pA1) + (pB0 - pB1);     // wire15 = bit0
        float ps = pA0 + pA1 + pB0 + pB1;
        #pragma unroll
        for (int q = 1; q < 15; q++)
            acc[q] += ((i0 >> (15 - q)) & 1) ? -ps : ps;
    }
    #pragma unroll
    for (int q = 0; q < NQ; q++){
        float v = acc[q];
        #pragma unroll
        for (int off = 16; off > 0; off >>= 1)
            v += __shfl_down_sync(0xffffffffu, v, off);
        acc[q] = v;
    }
    int w = tid >> 5, lane = tid & 31;
    if (lane == 0){
        #pragma unroll
        for (int q = 0; q < NQ; q++) sred[w][q] = acc[q];
    }
    __syncthreads();
    if (tid < NQ){
        float v = 0.f;
        #pragma unroll
        for (int w2 = 0; w2 < 8; w2++) v += sred[w2][tid];
        atomicAdd(&g_expv[b*NQ + tid], v);
    }
}

__global__ void fc_kernel(const float* __restrict__ fc_w, const float* __restrict__ fc_b,
                          float* __restrict__ out){
    int b = threadIdx.x;
    if (b >= NB) return;
    float f[NQ];
    #pragma unroll
    for (int q = 0; q < NQ; q++) f[q] = g_expv[b*NQ + q];
    float lg[NC];
    float mx = -1e30f;
    #pragma unroll
    for (int c = 0; c < NC; c++){
        float s = fc_b[c];
        #pragma unroll
        for (int q = 0; q < NQ; q++) s = fmaf(fc_w[c*NQ + q], f[q], s);
        lg[c] = s;
        mx = fmaxf(mx, s);
    }
    float se = 0.f;
    #pragma unroll
    for (int c = 0; c < NC; c++) se += expf(lg[c] - mx);
    float ls = logf(se);
    #pragma unroll
    for (int c = 0; c < NC; c++) out[b*NC + c] = lg[c] - mx - ls;
}

extern "C" void kernel_launch(void* const* d_in, const int* in_sizes, int n_in,
                              void* d_out, int out_size){
    const float* x   = (const float*)d_in[0];
    const float* w0  = (const float*)d_in[1];
    const float* x0  = (const float*)d_in[2];
    const float* w1  = (const float*)d_in[3];
    const float* x1  = (const float*)d_in[4];
    const float* fcw = (const float*)d_in[5];
    const float* fcb = (const float*)d_in[6];

    const int smem = NPAIR * sizeof(float4);   // 64 KB
    cudaFuncSetAttribute(k2_initB1, cudaFuncAttributeMaxDynamicSharedMemorySize, smem);
    cudaFuncSetAttribute(k3_passA2, cudaFuncAttributeMaxDynamicSharedMemorySize, smem);
    cudaFuncSetAttribute(k4_passB2, cudaFuncAttributeMaxDynamicSharedMemorySize, smem);

    dim3 grid(8, NB);
    k2_initB1<<<grid, TPB, smem>>>(x, w0, x0, w1, x1);
    k3_passA2<<<grid, TPB, smem>>>(x, x0, w1, x1);
    k4_passB2<<<grid, TPB, smem>>>(x, w1, x1);
    k5_expv  <<<grid, TPB>>>(x1);
    fc_kernel<<<1, 64>>>(fcw, fcb, (float*)d_out);
}

// round 7
// speedup vs baseline: 1.7055x; 1.2120x over previous
#include <cuda_runtime.h>

#define NQ  16
#define DIM 65536
#define NB  64
#define NC  23
#define TPB 256
#define NPAIR 4096   // float4 pairs per 64KB tile

// wire->amp-bit map sigma: w15->0 w11->1 w10->2 w9->3 w8->4 w7->5 w12->6 w13->7
//                          w14->8 w4->9 w5->10 w6->11 w3->12 w0->13 w1->14 w2->15
__device__ float2 g_state[NB * DIM];   // 32 MB scratch
__device__ float  g_expv[NB * NQ];

struct P2 { float2 lo, hi; };          // lo: amp bit0=0 (wire15=0), hi: bit0=1

__device__ __forceinline__ float2 cmulf(float2 a, float2 b){
    return make_float2(a.x*b.x - a.y*b.y, a.x*b.y + a.y*b.x);
}
__device__ __forceinline__ void ap1q(float2 &v0, float2 &v1,
                                     float2 u00, float2 u01, float2 u10, float2 u11){
    float2 a = v0, b = v1;
    v0.x = u00.x*a.x - u00.y*a.y + u01.x*b.x - u01.y*b.y;
    v0.y = u00.x*a.y + u00.y*a.x + u01.x*b.y + u01.y*b.x;
    v1.x = u10.x*a.x - u10.y*a.y + u11.x*b.x - u11.y*b.y;
    v1.y = u10.x*a.y + u10.y*a.x + u11.x*b.y + u11.y*b.x;
}
// RX(theta): [[c, -i s], [-i s, c]] with c=cos(t/2), s=sin(t/2)
__device__ __forceinline__ void aprx(float2 &v0, float2 &v1, float c, float s){
    float2 a = v0, b = v1;
    v0 = make_float2(fmaf(c, a.x,  s*b.y), fmaf(c, a.y, -s*b.x));
    v1 = make_float2(fmaf(c, b.x,  s*a.y), fmaf(c, b.y, -s*a.x));
}
__device__ __forceinline__ int FP(int p){ return p ^ ((p>>3)&7) ^ ((p>>6)&7); }

__device__ __forceinline__ P2 ld4(const float4* S, int i){
    float4 t = S[i]; P2 r; r.lo = make_float2(t.x,t.y); r.hi = make_float2(t.z,t.w); return r;
}
__device__ __forceinline__ void st4(float4* S, int i, P2 v){
    S[i] = make_float4(v.lo.x, v.lo.y, v.hi.x, v.hi.y);
}

// Fused U = Rot(w[q]) * RX(x[b,q]); CRX params (cos, sin) of half-angle.
__device__ __forceinline__ void setup_one(const float* __restrict__ x,
                                          const float* __restrict__ w,
                                          const float* __restrict__ xc,
                                          int b, int q, float2 (*sU)[4], float2* sCX){
    float xv = x[b*NQ + q];
    float hc = cosf(0.5f*xv), hs = sinf(0.5f*xv);
    float phi = w[q*3+0], th = w[q*3+1], om = w[q*3+2];
    float ct = cosf(0.5f*th), st = sinf(0.5f*th);
    float pp = 0.5f*(phi+om), mm = 0.5f*(phi-om);
    float2 A  = make_float2( cosf(pp)*ct, -sinf(pp)*ct);
    float2 Bm = make_float2(-cosf(mm)*st, -sinf(mm)*st);
    float2 C  = make_float2( cosf(mm)*st, -sinf(mm)*st);
    float2 D  = make_float2( cosf(pp)*ct,  sinf(pp)*ct);
    sU[q][0] = make_float2(A.x*hc + Bm.y*hs,   A.y*hc - Bm.x*hs);
    sU[q][1] = make_float2(A.y*hs + Bm.x*hc,  -A.x*hs + Bm.y*hc);
    sU[q][2] = make_float2(C.x*hc + D.y*hs,    C.y*hc - D.x*hs);
    sU[q][3] = make_float2(C.y*hs + D.x*hc,   -C.x*hs + D.y*hc);
    float cv = xc[q];
    sCX[q] = make_float2(cosf(0.5f*cv), sinf(0.5f*cv));
}

// ---- gate helpers on P2 arrays ----
template<int N, int K>
__device__ __forceinline__ void g1q(P2* v, const float2* u){
    float2 u00 = u[0], u01 = u[1], u10 = u[2], u11 = u[3];
    #pragma unroll
    for (int m = 0; m < N; m++)
        if (!(m & (1 << K))){
            ap1q(v[m].lo, v[m | (1 << K)].lo, u00, u01, u10, u11);
            ap1q(v[m].hi, v[m | (1 << K)].hi, u00, u01, u10, u11);
        }
}
template<int N, int KC, int KT>
__device__ __forceinline__ void gcrx(P2* v, float2 cs){
    #pragma unroll
    for (int m = 0; m < N; m++)
        if ((m & (1 << KC)) && !(m & (1 << KT))){
            aprx(v[m].lo, v[m | (1 << KT)].lo, cs.x, cs.y);
            aprx(v[m].hi, v[m | (1 << KT)].hi, cs.x, cs.y);
        }
}
template<int N>
__device__ __forceinline__ void g1q_pair(P2* v, const float2* u){
    float2 u00 = u[0], u01 = u[1], u10 = u[2], u11 = u[3];
    #pragma unroll
    for (int m = 0; m < N; m++) ap1q(v[m].lo, v[m].hi, u00, u01, u10, u11);
}
template<int N, int KC>
__device__ __forceinline__ void gcrx_tgtpair(P2* v, float2 cs){
    #pragma unroll
    for (int m = 0; m < N; m++)
        if (m & (1 << KC)) aprx(v[m].lo, v[m].hi, cs.x, cs.y);
}
template<int N, int KT>
__device__ __forceinline__ void gcrx_ctrlpair(P2* v, float2 cs){
    #pragma unroll
    for (int m = 0; m < N; m++)
        if (!(m & (1 << KT))) aprx(v[m].hi, v[m | (1 << KT)].hi, cs.x, cs.y);
}

// ---------------------------------------------------------------------------
// P1: analytic init (all 16 L1 1q + L1 CRX0,1,2 via tables) + L1 CRX3..14
//     + fused L2 1q w3..w14.  Tile t = amp bits {13,14,15} (w0,w1,w2).
//     Locals = amp bits 12..0; pair p = amp bits 12..1.  Write-only.
// p-bit -> wire: p0..p7 = w11,w10,w9,w8,w7,w12,w13,w14; p8=w4 p9=w5 p10=w6 p11=w3
// ---------------------------------------------------------------------------
__global__ void __launch_bounds__(TPB, 2)
p1_init(const float* __restrict__ x, const float* __restrict__ w0,
        const float* __restrict__ x0, const float* __restrict__ w1,
        const float* __restrict__ x1){
    extern __shared__ float4 S[];
    __shared__ float2 sU1[NQ][4], sU2[NQ][4];
    __shared__ float2 sCX1[NQ], sCX2d[NQ];
    __shared__ float2 sT4x[16];
    __shared__ float2 sTb[8];
    __shared__ float4 sTa[256];
    int tid = threadIdx.x, t = blockIdx.x, b = blockIdx.y;
    if (tid < 16)      setup_one(x, w0, x0, b, tid,      sU1, sCX1);
    else if (tid < 32) setup_one(x, w1, x1, b, tid - 16, sU2, sCX2d);
    if (t == 0 && tid >= 32 && tid < 48) g_expv[b*NQ + (tid-32)] = 0.f;
    __syncthreads();

    // Ta over amp bits 1..8 (wires 11,10,9,8,7,12,13,14) + pair (w15)
    {
        int s8 = tid;
        float2 a = sU1[11][(s8&1)?2:0];
        a = cmulf(a, sU1[10][((s8>>1)&1)?2:0]);
        a = cmulf(a, sU1[ 9][((s8>>2)&1)?2:0]);
        a = cmulf(a, sU1[ 8][((s8>>3)&1)?2:0]);
        a = cmulf(a, sU1[ 7][((s8>>4)&1)?2:0]);
        a = cmulf(a, sU1[12][((s8>>5)&1)?2:0]);
        a = cmulf(a, sU1[13][((s8>>6)&1)?2:0]);
        a = cmulf(a, sU1[14][((s8>>7)&1)?2:0]);
        float2 lo = cmulf(a, sU1[15][0]);
        float2 hi = cmulf(a, sU1[15][2]);
        sTa[s8] = make_float4(lo.x, lo.y, hi.x, hi.y);
    }
    if (tid < 8){   // Tb over amp bits 9,10,11 (wires 4,5,6): j2=b9 j1=b10 j0=b11
        int j = tid;
        float2 a2 = cmulf(sU1[4][((j>>2)&1)?2:0], sU1[5][((j>>1)&1)?2:0]);
        sTb[j] = cmulf(a2, sU1[6][(j&1)?2:0]);
    }
    if (tid >= 16 && tid < 32){  // T4x over (w0,w1,w2,w3): m3=w0 m2=w1 m1=w2 m0=w3
        int m = tid - 16;
        float2 a2 = cmulf(sU1[0][((m>>3)&1)?2:0], sU1[1][((m>>2)&1)?2:0]);
        a2 = cmulf(a2, sU1[2][((m>>1)&1)?2:0]);
        sT4x[m] = cmulf(a2, sU1[3][(m&1)?2:0]);
    }
    __syncthreads();
    if (tid < 4){ float2 cs = sCX1[0]; aprx(sT4x[8+tid], sT4x[12+tid], cs.x, cs.y); }
    __syncthreads();
    if (tid < 4){ float2 cs = sCX1[1]; int m = (tid&1) | ((tid>>1)<<3) | 4;
                  aprx(sT4x[m], sT4x[m|2], cs.x, cs.y); }
    __syncthreads();
    if (tid < 4){ float2 cs = sCX1[2]; int m = 2 + 4*tid;
                  aprx(sT4x[m], sT4x[m|1], cs.x, cs.y); }
    __syncthreads();

    // Fill tile: t bit0 = amp13(w0), bit1 = amp14(w1), bit2 = amp15(w2)
    #pragma unroll
    for (int k = 0; k < 16; k++){
        int p = tid + (k << 8);
        int m = ((t&1)<<3) | (((t>>1)&1)<<2) | (((t>>2)&1)<<1) | ((p>>11)&1);
        int j = (((p>>8)&1)<<2) | (((p>>9)&1)<<1) | ((p>>10)&1);
        float2 c = cmulf(sT4x[m], sTb[j]);
        float4 ta = sTa[p & 255];
        P2 v;
        v.lo = cmulf(c, make_float2(ta.x, ta.y));
        v.hi = cmulf(c, make_float2(ta.z, ta.w));
        st4(S, FP(p), v);
    }
    __syncthreads();

    // rA v16 ext: m3=p11 m2=p8 m1=p9 m0=p10 : CRX3(11,8) CRX4(8,9) CRX5(9,10) + 1q w3,w4,w5
    { P2 v[16]; int base = tid;
      #pragma unroll
      for (int m = 0; m < 16; m++){
        int p = base | (((m>>2)&1)<<8) | (((m>>1)&1)<<9) | ((m&1)<<10) | (((m>>3)&1)<<11);
        v[m] = ld4(S, FP(p));
      }
      gcrx<16,3,2>(v, sCX1[3]); g1q<16,3>(v, sU2[3]);
      gcrx<16,2,1>(v, sCX1[4]); g1q<16,2>(v, sU2[4]);
      gcrx<16,1,0>(v, sCX1[5]); g1q<16,1>(v, sU2[5]);
      #pragma unroll
      for (int m = 0; m < 16; m++){
        int p = base | (((m>>2)&1)<<8) | (((m>>1)&1)<<9) | ((m&1)<<10) | (((m>>3)&1)<<11);
        st4(S, FP(p), v[m]);
      }
    }
    __syncthreads();
    // rB v8 ext: m2=p10 m1=p4 m0=p3 : CRX6(10,4) CRX7(4,3) + 1q w6,w7
    #pragma unroll
    for (int it = 0; it < 2; it++){
      P2 v[8]; int g = tid + (it<<8);
      int base = (g & 7) | (((g>>3)&31)<<5) | (((g>>8)&1)<<11);
      #pragma unroll
      for (int m = 0; m < 8; m++){
        int p = base | (((m>>2)&1)<<10) | (((m>>1)&1)<<4) | ((m&1)<<3);
        v[m] = ld4(S, FP(p));
      }
      gcrx<8,2,1>(v, sCX1[6]); g1q<8,2>(v, sU2[6]);
      gcrx<8,1,0>(v, sCX1[7]); g1q<8,1>(v, sU2[7]);
      #pragma unroll
      for (int m = 0; m < 8; m++){
        int p = base | (((m>>2)&1)<<10) | (((m>>1)&1)<<4) | ((m&1)<<3);
        st4(S, FP(p), v[m]);
      }
    }
    __syncthreads();
    // rC v16 ext: m3=p3 m2=p2 m1=p1 m0=p0 : CRX8(3,2) CRX9(2,1) CRX10(1,0) + 1q w8,w9,w10
    { P2 v[16]; int base = tid << 4;
      #pragma unroll
      for (int m = 0; m < 16; m++) v[m] = ld4(S, FP(base | m));
      gcrx<16,3,2>(v, sCX1[8]);  g1q<16,3>(v, sU2[8]);
      gcrx<16,2,1>(v, sCX1[9]);  g1q<16,2>(v, sU2[9]);
      gcrx<16,1,0>(v, sCX1[10]); g1q<16,1>(v, sU2[10]);
      #pragma unroll
      for (int m = 0; m < 16; m++) st4(S, FP(base | m), v[m]);
    }
    __syncthreads();
    // rD v16 ext: m3=p0 m2=p5 m1=p6 m0=p7 : CRX11(0,5) CRX12(5,6) CRX13(6,7) CRX14(7,pair)
    //             + 1q w11,w12,w13,w14
    { P2 v[16]; int g = tid;
      int base = ((g & 15) << 1) | ((g >> 4) << 8);
      #pragma unroll
      for (int m = 0; m < 16; m++){
        int p = base | ((m>>3)&1) | (((m>>2)&1)<<5) | (((m>>1)&1)<<6) | ((m&1)<<7);
        v[m] = ld4(S, FP(p));
      }
      gcrx<16,3,2>(v, sCX1[11]); g1q<16,3>(v, sU2[11]);
      gcrx<16,2,1>(v, sCX1[12]); g1q<16,2>(v, sU2[12]);
      gcrx<16,1,0>(v, sCX1[13]); g1q<16,1>(v, sU2[13]);
      gcrx_tgtpair<16,0>(v, sCX1[14]); g1q<16,0>(v, sU2[14]);
      #pragma unroll
      for (int m = 0; m < 16; m++){
        int p = base | ((m>>3)&1) | (((m>>2)&1)<<5) | (((m>>1)&1)<<6) | ((m&1)<<7);
        st4(S, FP(p), v[m]);
      }
    }
    __syncthreads();

    float4* go = (float4*)(g_state + b*DIM) + (t << 12);
    #pragma unroll
    for (int k = 0; k < 16; k++){ int p = tid + (k << 8); go[p] = S[FP(p)]; }
}

// ---------------------------------------------------------------------------
// P2: L1 CRX15 + L2 1q w15,w0,w1,w2 + L2 CRX0..7.
// Tile t = amp bits {6,7,8} (w12,w13,w14); locals amp {0..5, 9..15}.
// p0..p4 = amp1..5 (w11,w10,w9,w8,w7); p5..p11 = amp9..15 (w4,w5,w6,w3,w0,w1,w2)
// gmem: pr = (p&31) | (t<<5) | ((p>>5)<<8)
// ---------------------------------------------------------------------------
__global__ void __launch_bounds__(TPB, 2)
p2_mid(const float* __restrict__ x, const float* __restrict__ x0,
       const float* __restrict__ w1, const float* __restrict__ x1){
    extern __shared__ float4 S[];
    __shared__ float2 sU2[NQ][4], sCX2[NQ];
    __shared__ float2 c15s;
    int tid = threadIdx.x, t = blockIdx.x, b = blockIdx.y;
    if (tid < 16) setup_one(x, w1, x1, b, tid, sU2, sCX2);
    else if (tid == 16){
        float cv = x0[15];
        c15s = make_float2(cosf(0.5f*cv), sinf(0.5f*cv));
    }
    __syncthreads();

    const float4* g4 = (const float4*)(g_state + b*DIM);
    #pragma unroll
    for (int k = 0; k < 16; k++){
        int p = tid + (k << 8);
        int pr = (p & 31) | (t << 5) | ((p >> 5) << 8);
        S[FP(p)] = g4[pr];
    }
    __syncthreads();

    // r0 v8 ext: m2=p9(w0) m1=p10(w1) m0=p11(w2), pair=w15
    {
      float2 c15 = c15s;
      #pragma unroll
      for (int it = 0; it < 2; it++){
        P2 v[8]; int g = tid + (it<<8);
        #pragma unroll
        for (int m = 0; m < 8; m++){
          int p = g | (((m>>2)&1)<<9) | (((m>>1)&1)<<10) | ((m&1)<<11);
          v[m] = ld4(S, FP(p));
        }
        gcrx_ctrlpair<8,2>(v, c15);          // CRX15(L1): w15 -> w0
        g1q_pair<8>(v, sU2[15]);
        g1q<8,2>(v, sU2[0]); g1q<8,1>(v, sU2[1]); g1q<8,0>(v, sU2[2]);
        gcrx<8,2,1>(v, sCX2[0]);             // CRX0(L2)
        gcrx<8,1,0>(v, sCX2[1]);             // CRX1(L2)
        #pragma unroll
        for (int m = 0; m < 8; m++){
          int p = g | (((m>>2)&1)<<9) | (((m>>1)&1)<<10) | ((m&1)<<11);
          st4(S, FP(p), v[m]);
        }
      }
    }
    __syncthreads();
    // r1 v16 ext: m3=p11(w2) m2=p8(w3) m1=p5(w4) m0=p6(w5) : CRX2,3,4
    { P2 v[16]; int g = tid;
      int base = (g & 31) | (((g>>5)&1)<<7) | (((g>>6)&3)<<9);
      #pragma unroll
      for (int m = 0; m < 16; m++){
        int p = base | (((m>>3)&1)<<11) | (((m>>2)&1)<<8) | (((m>>1)&1)<<5) | ((m&1)<<6);
        v[m] = ld4(S, FP(p));
      }
      gcrx<16,3,2>(v, sCX2[2]); gcrx<16,2,1>(v, sCX2[3]); gcrx<16,1,0>(v, sCX2[4]);
      #pragma unroll
      for (int m = 0; m < 16; m++){
        int p = base | (((m>>3)&1)<<11) | (((m>>2)&1)<<8) | (((m>>1)&1)<<5) | ((m&1)<<6);
        st4(S, FP(p), v[m]);
      }
    }
    __syncthreads();
    // r2 v16 ext: m3=p6(w5) m2=p7(w6) m1=p4(w7) m0=p3(w8) : CRX5,6,7
    { P2 v[16]; int g = tid;
      int base = (g & 7) | (((g>>3)&1)<<5) | ((g>>4)<<8);
      #pragma unroll
      for (int m = 0; m < 16; m++){
        int p = base | (((m>>3)&1)<<6) | (((m>>2)&1)<<7) | (((m>>1)&1)<<4) | ((m&1)<<3);
        v[m] = ld4(S, FP(p));
      }
      gcrx<16,3,2>(v, sCX2[5]); gcrx<16,2,1>(v, sCX2[6]); gcrx<16,1,0>(v, sCX2[7]);
      #pragma unroll
      for (int m = 0; m < 16; m++){
        int p = base | (((m>>3)&1)<<6) | (((m>>2)&1)<<7) | (((m>>1)&1)<<4) | ((m&1)<<3);
        st4(S, FP(p), v[m]);
      }
    }
    __syncthreads();

    float4* go = (float4*)(g_state + b*DIM);
    #pragma unroll
    for (int k = 0; k < 16; k++){
        int p = tid + (k << 8);
        int pr = (p & 31) | (t << 5) | ((p >> 5) << 8);
        go[pr] = S[FP(p)];
    }
}

// ---------------------------------------------------------------------------
// P3: L2 CRX8..14 + CRX15 + PauliZ expvals (no write-back).
// Tile t = amp bits {9,10,11} (w4,w5,w6); locals amp {0..8, 12..15}.
// p0..p7 = amp1..8 (w11,w10,w9,w8,w7,w12,w13,w14); p8..p11 = amp12..15 (w3,w0,w1,w2)
// gmem: pr = (p&255) | (t<<8) | ((p>>8)<<11)
// ---------------------------------------------------------------------------
__global__ void __launch_bounds__(TPB, 2)
p3_final(const float* __restrict__ x1){
    extern __shared__ float4 S[];
    __shared__ float2 sCX2[NQ];
    __shared__ float sred[8][NQ];
    int tid = threadIdx.x, t = blockIdx.x, b = blockIdx.y;
    if (tid < 16){
        float cv = x1[tid];
        sCX2[tid] = make_float2(cosf(0.5f*cv), sinf(0.5f*cv));
    }
    __syncthreads();

    const float4* g4 = (const float4*)(g_state + b*DIM);
    #pragma unroll
    for (int k = 0; k < 16; k++){
        int p = tid + (k << 8);
        int pr = (p & 255) | (t << 8) | ((p >> 8) << 11);
        S[FP(p)] = g4[pr];
    }
    __syncthreads();

    // r0 v16 ext: m3=p3(w8) m2=p2(w9) m1=p1(w10) m0=p0(w11) : CRX8,9,10
    { P2 v[16]; int base = tid << 4;
      #pragma unroll
      for (int m = 0; m < 16; m++) v[m] = ld4(S, FP(base | m));
      gcrx<16,3,2>(v, sCX2[8]); gcrx<16,2,1>(v, sCX2[9]); gcrx<16,1,0>(v, sCX2[10]);
      #pragma unroll
      for (int m = 0; m < 16; m++) st4(S, FP(base | m), v[m]);
    }
    __syncthreads();
    // r1 v16 ext: m3=p0(w11) m2=p5(w12) m1=p6(w13) m0=p7(w14) : CRX11,12,13,14(pair)
    { P2 v[16]; int g = tid;
      int base = ((g & 15) << 1) | ((g >> 4) << 8);
      #pragma unroll
      for (int m = 0; m < 16; m++){
        int p = base | ((m>>3)&1) | (((m>>2)&1)<<5) | (((m>>1)&1)<<6) | ((m&1)<<7);
        v[m] = ld4(S, FP(p));
      }
      gcrx<16,3,2>(v, sCX2[11]); gcrx<16,2,1>(v, sCX2[12]);
      gcrx<16,1,0>(v, sCX2[13]); gcrx_tgtpair<16,0>(v, sCX2[14]);
      #pragma unroll
      for (int m = 0; m < 16; m++){
        int p = base | ((m>>3)&1) | (((m>>2)&1)<<5) | (((m>>1)&1)<<6) | ((m&1)<<7);
        st4(S, FP(p), v[m]);
      }
    }
    __syncthreads();

    // CRX15(L2) (ctrl pair, tgt w0 = p9) fused with expval accumulation.
    float2 c15 = sCX2[15];
    float acc[NQ];
    #pragma unroll
    for (int q = 0; q < NQ; q++) acc[q] = 0.f;
    float pstot = 0.f;
    #pragma unroll
    for (int it = 0; it < 8; it++){
        int j = tid + (it << 8);
        int p = (j & 511) | ((j >> 9) << 10);      // p9 = 0
        P2 v0 = ld4(S, FP(p));
        P2 v1 = ld4(S, FP(p | 512));
        aprx(v0.hi, v1.hi, c15.x, c15.y);
        float pA0 = v0.lo.x*v0.lo.x + v0.lo.y*v0.lo.y;
        float pA1 = v0.hi.x*v0.hi.x + v0.hi.y*v0.hi.y;
        float pB0 = v1.lo.x*v1.lo.x + v1.lo.y*v1.lo.y;
        float pB1 = v1.hi.x*v1.hi.x + v1.hi.y*v1.hi.y;
        float ps = pA0 + pA1 + pB0 + pB1;
        pstot += ps;
        acc[0]  += (pA0 + pA1) - (pB0 + pB1);      // w0  = p9
        acc[15] += (pA0 - pA1) + (pB0 - pB1);      // w15 = pair
        acc[11] += (p & 1)    ? -ps : ps;
        acc[10] += (p & 2)    ? -ps : ps;
        acc[9]  += (p & 4)    ? -ps : ps;
        acc[8]  += (p & 8)    ? -ps : ps;
        acc[7]  += (p & 16)   ? -ps : ps;
        acc[12] += (p & 32)   ? -ps : ps;
        acc[13] += (p & 64)   ? -ps : ps;
        acc[14] += (p & 128)  ? -ps : ps;
        acc[3]  += (p & 256)  ? -ps : ps;
        acc[1]  += (p & 1024) ? -ps : ps;
        acc[2]  += (p & 2048) ? -ps : ps;
    }
    acc[4] = (t & 1) ? -pstot : pstot;
    acc[5] = (t & 2) ? -pstot : pstot;
    acc[6] = (t & 4) ? -pstot : pstot;

    #pragma unroll
    for (int q = 0; q < NQ; q++){
        float v = acc[q];
        #pragma unroll
        for (int off = 16; off > 0; off >>= 1)
            v += __shfl_down_sync(0xffffffffu, v, off);
        acc[q] = v;
    }
    int w = tid >> 5, lane = tid & 31;
    if (lane == 0){
        #pragma unroll
        for (int q = 0; q < NQ; q++) sred[w][q] = acc[q];
    }
    __syncthreads();
    if (tid < NQ){
        float v = 0.f;
        #pragma unroll
        for (int w2 = 0; w2 < 8; w2++) v += sred[w2][tid];
        atomicAdd(&g_expv[b*NQ + tid], v);
    }
}

__global__ void fc_kernel(const float* __restrict__ fc_w, const float* __restrict__ fc_b,
                          float* __restrict__ out){
    int b = threadIdx.x;
    if (b >= NB) return;
    float f[NQ];
    #pragma unroll
    for (int q = 0; q < NQ; q++) f[q] = g_expv[b*NQ + q];
    float lg[NC];
    float mx = -1e30f;
    #pragma unroll
    for (int c = 0; c < NC; c++){
        float s = fc_b[c];
        #pragma unroll
        for (int q = 0; q < NQ; q++) s = fmaf(fc_w[c*NQ + q], f[q], s);
        lg[c] = s;
        mx = fmaxf(mx, s);
    }
    float se = 0.f;
    #pragma unroll
    for (int c = 0; c < NC; c++) se += expf(lg[c] - mx);
    float ls = logf(se);
    #pragma unroll
    for (int c = 0; c < NC; c++) out[b*NC + c] = lg[c] - mx - ls;
}

extern "C" void kernel_launch(void* const* d_in, const int* in_sizes, int n_in,
                              void* d_out, int out_size){
    const float* x   = (const float*)d_in[0];
    const float* w0  = (const float*)d_in[1];
    const float* x0  = (const float*)d_in[2];
    const float* w1  = (const float*)d_in[3];
    const float* x1  = (const float*)d_in[4];
    const float* fcw = (const float*)d_in[5];
    const float* fcb = (const float*)d_in[6];

    const int smem = NPAIR * sizeof(float4);   // 64 KB
    cudaFuncSetAttribute(p1_init,  cudaFuncAttributeMaxDynamicSharedMemorySize, smem);
    cudaFuncSetAttribute(p2_mid,   cudaFuncAttributeMaxDynamicSharedMemorySize, smem);
    cudaFuncSetAttribute(p3_final, cudaFuncAttributeMaxDynamicSharedMemorySize, smem);

    dim3 grid(8, NB);
    p1_init <<<grid, TPB, smem>>>(x, w0, x0, w1, x1);
    p2_mid  <<<grid, TPB, smem>>>(x, x0, w1, x1);
    p3_final<<<grid, TPB, smem>>>(x1);
    fc_kernel<<<1, 64>>>(fcw, fcb, (float*)d_out);
}

// round 10
// speedup vs baseline: 1.7195x; 1.0082x over previous
#include <cuda_runtime.h>

#define NQ  16
#define DIM 65536
#define NB  64
#define NC  23
#define TPB 256
#define NPAIR 4096   // float4 pairs per 64KB tile

// wire->amp-bit map sigma: w15->0 w11->1 w10->2 w9->3 w8->4 w7->5 w12->6 w13->7
//                          w14->8 w4->9 w5->10 w6->11 w3->12 w0->13 w1->14 w2->15
__device__ float2 g_state[NB * DIM];   // 32 MB scratch
__device__ float  g_expv[NB * NQ];
__device__ int    g_cnt[NB];

struct P2 { float2 lo, hi; };          // lo: amp bit0=0 (wire15=0), hi: bit0=1

__device__ __forceinline__ float2 cmulf(float2 a, float2 b){
    return make_float2(a.x*b.x - a.y*b.y, a.x*b.y + a.y*b.x);
}
__device__ __forceinline__ void ap1q(float2 &v0, float2 &v1,
                                     float2 u00, float2 u01, float2 u10, float2 u11){
    float2 a = v0, b = v1;
    v0.x = u00.x*a.x - u00.y*a.y + u01.x*b.x - u01.y*b.y;
    v0.y = u00.x*a.y + u00.y*a.x + u01.x*b.y + u01.y*b.x;
    v1.x = u10.x*a.x - u10.y*a.y + u11.x*b.x - u11.y*b.y;
    v1.y = u10.x*a.y + u10.y*a.x + u11.x*b.y + u11.y*b.x;
}
// RX(theta): [[c, -i s], [-i s, c]] with c=cos(t/2), s=sin(t/2)
__device__ __forceinline__ void aprx(float2 &v0, float2 &v1, float c, float s){
    float2 a = v0, b = v1;
    v0 = make_float2(fmaf(c, a.x,  s*b.y), fmaf(c, a.y, -s*b.x));
    v1 = make_float2(fmaf(c, b.x,  s*a.y), fmaf(c, b.y, -s*a.x));
}
__device__ __forceinline__ int FP(int p){ return p ^ ((p>>3)&7) ^ ((p>>6)&7); }

__device__ __forceinline__ P2 ld4(const float4* S, int i){
    float4 t = S[i]; P2 r; r.lo = make_float2(t.x,t.y); r.hi = make_float2(t.z,t.w); return r;
}
__device__ __forceinline__ void st4(float4* S, int i, P2 v){
    S[i] = make_float4(v.lo.x, v.lo.y, v.hi.x, v.hi.y);
}

// Fused U = Rot(w[q]) * RX(x[b,q]); CRX params (cos, sin) of half-angle.
__device__ __forceinline__ void setup_one(const float* __restrict__ x,
                                          const float* __restrict__ w,
                                          const float* __restrict__ xc,
                                          int b, int q, float2 (*sU)[4], float2* sCX){
    float xv = x[b*NQ + q];
    float hc = cosf(0.5f*xv), hs = sinf(0.5f*xv);
    float phi = w[q*3+0], th = w[q*3+1], om = w[q*3+2];
    float ct = cosf(0.5f*th), st = sinf(0.5f*th);
    float pp = 0.5f*(phi+om), mm = 0.5f*(phi-om);
    float2 A  = make_float2( cosf(pp)*ct, -sinf(pp)*ct);
    float2 Bm = make_float2(-cosf(mm)*st, -sinf(mm)*st);
    float2 C  = make_float2( cosf(mm)*st, -sinf(mm)*st);
    float2 D  = make_float2( cosf(pp)*ct,  sinf(pp)*ct);
    sU[q][0] = make_float2(A.x*hc + Bm.y*hs,   A.y*hc - Bm.x*hs);
    sU[q][1] = make_float2(A.y*hs + Bm.x*hc,  -A.x*hs + Bm.y*hc);
    sU[q][2] = make_float2(C.x*hc + D.y*hs,    C.y*hc - D.x*hs);
    sU[q][3] = make_float2(C.y*hs + D.x*hc,   -C.x*hs + D.y*hc);
    float cv = xc[q];
    sCX[q] = make_float2(cosf(0.5f*cv), sinf(0.5f*cv));
}

// ---- gate helpers on P2 arrays ----
template<int N, int K>
__device__ __forceinline__ void g1q(P2* v, const float2* u){
    float2 u00 = u[0], u01 = u[1], u10 = u[2], u11 = u[3];
    #pragma unroll
    for (int m = 0; m < N; m++)
        if (!(m & (1 << K))){
            ap1q(v[m].lo, v[m | (1 << K)].lo, u00, u01, u10, u11);
            ap1q(v[m].hi, v[m | (1 << K)].hi, u00, u01, u10, u11);
        }
}
template<int N, int KC, int KT>
__device__ __forceinline__ void gcrx(P2* v, float2 cs){
    #pragma unroll
    for (int m = 0; m < N; m++)
        if ((m & (1 << KC)) && !(m & (1 << KT))){
            aprx(v[m].lo, v[m | (1 << KT)].lo, cs.x, cs.y);
            aprx(v[m].hi, v[m | (1 << KT)].hi, cs.x, cs.y);
        }
}
template<int N>
__device__ __forceinline__ void g1q_pair(P2* v, const float2* u){
    float2 u00 = u[0], u01 = u[1], u10 = u[2], u11 = u[3];
    #pragma unroll
    for (int m = 0; m < N; m++) ap1q(v[m].lo, v[m].hi, u00, u01, u10, u11);
}
template<int N, int KC>
__device__ __forceinline__ void gcrx_tgtpair(P2* v, float2 cs){
    #pragma unroll
    for (int m = 0; m < N; m++)
        if (m & (1 << KC)) aprx(v[m].lo, v[m].hi, cs.x, cs.y);
}
template<int N, int KT>
__device__ __forceinline__ void gcrx_ctrlpair(P2* v, float2 cs){
    #pragma unroll
    for (int m = 0; m < N; m++)
        if (!(m & (1 << KT))) aprx(v[m].hi, v[m | (1 << KT)].hi, cs.x, cs.y);
}

// ---------------------------------------------------------------------------
// P1: analytic init (all 16 L1 1q + L1 CRX0,1,2 via tables) + L1 CRX3..14
//     + fused L2 1q w3..w14.  Tile t = amp bits {13,14,15} (w0,w1,w2).
//     Locals = amp bits 12..0; pair p = amp bits 12..1.  Write-only.
// p-bit -> wire: p0..p7 = w11,w10,w9,w8,w7,w12,w13,w14; p8=w4 p9=w5 p10=w6 p11=w3
// ---------------------------------------------------------------------------
__global__ void __launch_bounds__(TPB, 2)
p1_init(const float* __restrict__ x, const float* __restrict__ w0,
        const float* __restrict__ x0, const float* __restrict__ w1,
        const float* __restrict__ x1){
    extern __shared__ float4 S[];
    __shared__ float2 sU1[NQ][4], sU2[NQ][4];
    __shared__ float2 sCX1[NQ], sCX2d[NQ];
    __shared__ float2 sT4x[16];
    __shared__ float2 sTb[8];
    __shared__ float4 sTa[256];
    int tid = threadIdx.x, t = blockIdx.x, b = blockIdx.y;
    if (tid < 16)      setup_one(x, w0, x0, b, tid,      sU1, sCX1);
    else if (tid < 32) setup_one(x, w1, x1, b, tid - 16, sU2, sCX2d);
    if (t == 0 && tid >= 32 && tid < 48) g_expv[b*NQ + (tid-32)] = 0.f;
    if (t == 0 && tid == 48) g_cnt[b] = 0;
    __syncthreads();

    // Ta over amp bits 1..8 (wires 11,10,9,8,7,12,13,14) + pair (w15)
    {
        int s8 = tid;
        float2 a = sU1[11][(s8&1)?2:0];
        a = cmulf(a, sU1[10][((s8>>1)&1)?2:0]);
        a = cmulf(a, sU1[ 9][((s8>>2)&1)?2:0]);
        a = cmulf(a, sU1[ 8][((s8>>3)&1)?2:0]);
        a = cmulf(a, sU1[ 7][((s8>>4)&1)?2:0]);
        a = cmulf(a, sU1[12][((s8>>5)&1)?2:0]);
        a = cmulf(a, sU1[13][((s8>>6)&1)?2:0]);
        a = cmulf(a, sU1[14][((s8>>7)&1)?2:0]);
        float2 lo = cmulf(a, sU1[15][0]);
        float2 hi = cmulf(a, sU1[15][2]);
        sTa[s8] = make_float4(lo.x, lo.y, hi.x, hi.y);
    }
    if (tid < 8){   // Tb over amp bits 9,10,11 (wires 4,5,6): j2=b9 j1=b10 j0=b11
        int j = tid;
        float2 a2 = cmulf(sU1[4][((j>>2)&1)?2:0], sU1[5][((j>>1)&1)?2:0]);
        sTb[j] = cmulf(a2, sU1[6][(j&1)?2:0]);
    }
    if (tid >= 16 && tid < 32){  // T4x over (w0,w1,w2,w3): m3=w0 m2=w1 m1=w2 m0=w3
        int m = tid - 16;
        float2 a2 = cmulf(sU1[0][((m>>3)&1)?2:0], sU1[1][((m>>2)&1)?2:0]);
        a2 = cmulf(a2, sU1[2][((m>>1)&1)?2:0]);
        sT4x[m] = cmulf(a2, sU1[3][(m&1)?2:0]);
    }
    __syncthreads();
    if (tid < 4){ float2 cs = sCX1[0]; aprx(sT4x[8+tid], sT4x[12+tid], cs.x, cs.y); }
    __syncthreads();
    if (tid < 4){ float2 cs = sCX1[1]; int m = (tid&1) | ((tid>>1)<<3) | 4;
                  aprx(sT4x[m], sT4x[m|2], cs.x, cs.y); }
    __syncthreads();
    if (tid < 4){ float2 cs = sCX1[2]; int m = 2 + 4*tid;
                  aprx(sT4x[m], sT4x[m|1], cs.x, cs.y); }
    __syncthreads();

    // Fill tile: t bit0 = amp13(w0), bit1 = amp14(w1), bit2 = amp15(w2)
    #pragma unroll
    for (int k = 0; k < 16; k++){
        int p = tid + (k << 8);
        int m = ((t&1)<<3) | (((t>>1)&1)<<2) | (((t>>2)&1)<<1) | ((p>>11)&1);
        int j = (((p>>8)&1)<<2) | (((p>>9)&1)<<1) | ((p>>10)&1);
        float2 c = cmulf(sT4x[m], sTb[j]);
        float4 ta = sTa[p & 255];
        P2 v;
        v.lo = cmulf(c, make_float2(ta.x, ta.y));
        v.hi = cmulf(c, make_float2(ta.z, ta.w));
        st4(S, FP(p), v);
    }
    __syncthreads();

    // rA v16 ext: m3=p11 m2=p8 m1=p9 m0=p10 : CRX3(11,8) CRX4(8,9) CRX5(9,10) + 1q w3,w4,w5
    { P2 v[16]; int base = tid;
      #pragma unroll
      for (int m = 0; m < 16; m++){
        int p = base | (((m>>2)&1)<<8) | (((m>>1)&1)<<9) | ((m&1)<<10) | (((m>>3)&1)<<11);
        v[m] = ld4(S, FP(p));
      }
      gcrx<16,3,2>(v, sCX1[3]); g1q<16,3>(v, sU2[3]);
      gcrx<16,2,1>(v, sCX1[4]); g1q<16,2>(v, sU2[4]);
      gcrx<16,1,0>(v, sCX1[5]); g1q<16,1>(v, sU2[5]);
      #pragma unroll
      for (int m = 0; m < 16; m++){
        int p = base | (((m>>2)&1)<<8) | (((m>>1)&1)<<9) | ((m&1)<<10) | (((m>>3)&1)<<11);
        st4(S, FP(p), v[m]);
      }
    }
    __syncthreads();
    // rB v8 ext: m2=p10 m1=p4 m0=p3 : CRX6(10,4) CRX7(4,3) + 1q w6,w7
    #pragma unroll
    for (int it = 0; it < 2; it++){
      P2 v[8]; int g = tid + (it<<8);
      int base = (g & 7) | (((g>>3)&31)<<5) | (((g>>8)&1)<<11);
      #pragma unroll
      for (int m = 0; m < 8; m++){
        int p = base | (((m>>2)&1)<<10) | (((m>>1)&1)<<4) | ((m&1)<<3);
        v[m] = ld4(S, FP(p));
      }
      gcrx<8,2,1>(v, sCX1[6]); g1q<8,2>(v, sU2[6]);
      gcrx<8,1,0>(v, sCX1[7]); g1q<8,1>(v, sU2[7]);
      #pragma unroll
      for (int m = 0; m < 8; m++){
        int p = base | (((m>>2)&1)<<10) | (((m>>1)&1)<<4) | ((m&1)<<3);
        st4(S, FP(p), v[m]);
      }
    }
    __syncthreads();
    // rC v16 ext: m3=p3 m2=p2 m1=p1 m0=p0 : CRX8(3,2) CRX9(2,1) CRX10(1,0) + 1q w8,w9,w10
    { P2 v[16]; int base = tid << 4;
      #pragma unroll
      for (int m = 0; m < 16; m++) v[m] = ld4(S, FP(base | m));
      gcrx<16,3,2>(v, sCX1[8]);  g1q<16,3>(v, sU2[8]);
      gcrx<16,2,1>(v, sCX1[9]);  g1q<16,2>(v, sU2[9]);
      gcrx<16,1,0>(v, sCX1[10]); g1q<16,1>(v, sU2[10]);
      #pragma unroll
      for (int m = 0; m < 16; m++) st4(S, FP(base | m), v[m]);
    }
    __syncthreads();
    // rD v16 ext: m3=p0 m2=p5 m1=p6 m0=p7 : CRX11(0,5) CRX12(5,6) CRX13(6,7) CRX14(7,pair)
    //             + 1q w11,w12,w13,w14
    { P2 v[16]; int g = tid;
      int base = ((g & 15) << 1) | ((g >> 4) << 8);
      #pragma unroll
      for (int m = 0; m < 16; m++){
        int p = base | ((m>>3)&1) | (((m>>2)&1)<<5) | (((m>>1)&1)<<6) | ((m&1)<<7);
        v[m] = ld4(S, FP(p));
      }
      gcrx<16,3,2>(v, sCX1[11]); g1q<16,3>(v, sU2[11]);
      gcrx<16,2,1>(v, sCX1[12]); g1q<16,2>(v, sU2[12]);
      gcrx<16,1,0>(v, sCX1[13]); g1q<16,1>(v, sU2[13]);
      gcrx_tgtpair<16,0>(v, sCX1[14]); g1q<16,0>(v, sU2[14]);
      #pragma unroll
      for (int m = 0; m < 16; m++){
        int p = base | ((m>>3)&1) | (((m>>2)&1)<<5) | (((m>>1)&1)<<6) | ((m&1)<<7);
        st4(S, FP(p), v[m]);
      }
    }
    __syncthreads();

    float4* go = (float4*)(g_state + b*DIM) + (t << 12);
    #pragma unroll
    for (int k = 0; k < 16; k++){ int p = tid + (k << 8); go[p] = S[FP(p)]; }
}

// ---------------------------------------------------------------------------
// P2: L1 CRX15 + L2 1q w15,w0,w1,w2 + L2 CRX0..7.
// Tile t = amp bits {6,7,8} (w12,w13,w14); locals amp {0..5, 9..15}.
// p0..p4 = amp1..5 (w11,w10,w9,w8,w7); p5..p11 = amp9..15 (w4,w5,w6,w3,w0,w1,w2)
// gmem: pr = (p&31) | (t<<5) | ((p>>5)<<8)
// ---------------------------------------------------------------------------
__global__ void __launch_bounds__(TPB, 2)
p2_mid(const float* __restrict__ x, const float* __restrict__ x0,
       const float* __restrict__ w1, const float* __restrict__ x1){
    extern __shared__ float4 S[];
    __shared__ float2 sU2[NQ][4], sCX2[NQ];
    __shared__ float2 c15s;
    int tid = threadIdx.x, t = blockIdx.x, b = blockIdx.y;
    if (tid < 16) setup_one(x, w1, x1, b, tid, sU2, sCX2);
    else if (tid == 16){
        float cv = x0[15];
        c15s = make_float2(cosf(0.5f*cv), sinf(0.5f*cv));
    }
    __syncthreads();

    const float4* g4 = (const float4*)(g_state + b*DIM);
    #pragma unroll
    for (int k = 0; k < 16; k++){
        int p = tid + (k << 8);
        int pr = (p & 31) | (t << 5) | ((p >> 5) << 8);
        S[FP(p)] = g4[pr];
    }
    __syncthreads();

    // r0 v8 ext: m2=p9(w0) m1=p10(w1) m0=p11(w2), pair=w15
    {
      float2 c15 = c15s;
      #pragma unroll
      for (int it = 0; it < 2; it++){
        P2 v[8]; int g = tid + (it<<8);
        #pragma unroll
        for (int m = 0; m < 8; m++){
          int p = g | (((m>>2)&1)<<9) | (((m>>1)&1)<<10) | ((m&1)<<11);
          v[m] = ld4(S, FP(p));
        }
        gcrx_ctrlpair<8,2>(v, c15);          // CRX15(L1): w15 -> w0
        g1q_pair<8>(v, sU2[15]);
        g1q<8,2>(v, sU2[0]); g1q<8,1>(v, sU2[1]); g1q<8,0>(v, sU2[2]);
        gcrx<8,2,1>(v, sCX2[0]);             // CRX0(L2)
        gcrx<8,1,0>(v, sCX2[1]);             // CRX1(L2)
        #pragma unroll
        for (int m = 0; m < 8; m++){
          int p = g | (((m>>2)&1)<<9) | (((m>>1)&1)<<10) | ((m&1)<<11);
          st4(S, FP(p), v[m]);
        }
      }
    }
    __syncthreads();
    // r1 v16 ext: m3=p11(w2) m2=p8(w3) m1=p5(w4) m0=p6(w5) : CRX2,3,4
    { P2 v[16]; int g = tid;
      int base = (g & 31) | (((g>>5)&1)<<7) | (((g>>6)&3)<<9);
      #pragma unroll
      for (int m = 0; m < 16; m++){
        int p = base | (((m>>3)&1)<<11) | (((m>>2)&1)<<8) | (((m>>1)&1)<<5) | ((m&1)<<6);
        v[m] = ld4(S, FP(p));
      }
      gcrx<16,3,2>(v, sCX2[2]); gcrx<16,2,1>(v, sCX2[3]); gcrx<16,1,0>(v, sCX2[4]);
      #pragma unroll
      for (int m = 0; m < 16; m++){
        int p = base | (((m>>3)&1)<<11) | (((m>>2)&1)<<8) | (((m>>1)&1)<<5) | ((m&1)<<6);
        st4(S, FP(p), v[m]);
      }
    }
    __syncthreads();
    // r2 v16 ext: m3=p6(w5) m2=p7(w6) m1=p4(w7) m0=p3(w8) : CRX5,6,7
    { P2 v[16]; int g = tid;
      int base = (g & 7) | (((g>>3)&1)<<5) | ((g>>4)<<8);
      #pragma unroll
      for (int m = 0; m < 16; m++){
        int p = base | (((m>>3)&1)<<6) | (((m>>2)&1)<<7) | (((m>>1)&1)<<4) | ((m&1)<<3);
        v[m] = ld4(S, FP(p));
      }
      gcrx<16,3,2>(v, sCX2[5]); gcrx<16,2,1>(v, sCX2[6]); gcrx<16,1,0>(v, sCX2[7]);
      #pragma unroll
      for (int m = 0; m < 16; m++){
        int p = base | (((m>>3)&1)<<6) | (((m>>2)&1)<<7) | (((m>>1)&1)<<4) | ((m&1)<<3);
        st4(S, FP(p), v[m]);
      }
    }
    __syncthreads();

    float4* go = (float4*)(g_state + b*DIM);
    #pragma unroll
    for (int k = 0; k < 16; k++){
        int p = tid + (k << 8);
        int pr = (p & 31) | (t << 5) | ((p >> 5) << 8);
        go[pr] = S[FP(p)];
    }
}

// ---------------------------------------------------------------------------
// P3: L2 CRX8..14 + CRX15 + PauliZ expvals + per-batch last-CTA FC epilogue.
// Tile t = amp bits {9,10,11} (w4,w5,w6); locals amp {0..8, 12..15}.
// p0..p7 = amp1..8 (w11,w10,w9,w8,w7,w12,w13,w14); p8..p11 = amp12..15 (w3,w0,w1,w2)
// gmem: pr = (p&255) | (t<<8) | ((p>>8)<<11)
// ---------------------------------------------------------------------------
__global__ void __launch_bounds__(TPB, 2)
p3_final(const float* __restrict__ x1, const float* __restrict__ fc_w,
         const float* __restrict__ fc_b, float* __restrict__ out){
    extern __shared__ float4 S[];
    __shared__ float2 sCX2[NQ];
    __shared__ float sred[8][NQ];
    __shared__ int lastf;
    int tid = threadIdx.x, t = blockIdx.x, b = blockIdx.y;
    if (tid < 16){
        float cv = x1[tid];
        sCX2[tid] = make_float2(cosf(0.5f*cv), sinf(0.5f*cv));
    }
    __syncthreads();

    const float4* g4 = (const float4*)(g_state + b*DIM);
    #pragma unroll
    for (int k = 0; k < 16; k++){
        int p = tid + (k << 8);
        int pr = (p & 255) | (t << 8) | ((p >> 8) << 11);
        S[FP(p)] = g4[pr];
    }
    __syncthreads();

    // r0 v16 ext: m3=p3(w8) m2=p2(w9) m1=p1(w10) m0=p0(w11) : CRX8,9,10
    { P2 v[16]; int base = tid << 4;
      #pragma unroll
      for (int m = 0; m < 16; m++) v[m] = ld4(S, FP(base | m));
      gcrx<16,3,2>(v, sCX2[8]); gcrx<16,2,1>(v, sCX2[9]); gcrx<16,1,0>(v, sCX2[10]);
      #pragma unroll
      for (int m = 0; m < 16; m++) st4(S, FP(base | m), v[m]);
    }
    __syncthreads();
    // r1 v16 ext: m3=p0(w11) m2=p5(w12) m1=p6(w13) m0=p7(w14) : CRX11,12,13,14(pair)
    { P2 v[16]; int g = tid;
      int base = ((g & 15) << 1) | ((g >> 4) << 8);
      #pragma unroll
      for (int m = 0; m < 16; m++){
        int p = base | ((m>>3)&1) | (((m>>2)&1)<<5) | (((m>>1)&1)<<6) | ((m&1)<<7);
        v[m] = ld4(S, FP(p));
      }
      gcrx<16,3,2>(v, sCX2[11]); gcrx<16,2,1>(v, sCX2[12]);
      gcrx<16,1,0>(v, sCX2[13]); gcrx_tgtpair<16,0>(v, sCX2[14]);
      #pragma unroll
      for (int m = 0; m < 16; m++){
        int p = base | ((m>>3)&1) | (((m>>2)&1)<<5) | (((m>>1)&1)<<6) | ((m&1)<<7);
        st4(S, FP(p), v[m]);
      }
    }
    __syncthreads();

    // CRX15(L2) (ctrl pair, tgt w0 = p9) fused with expval accumulation.
    float2 c15 = sCX2[15];
    float acc[NQ];
    #pragma unroll
    for (int q = 0; q < NQ; q++) acc[q] = 0.f;
    float pstot = 0.f;
    #pragma unroll
    for (int it = 0; it < 8; it++){
        int j = tid + (it << 8);
        int p = (j & 511) | ((j >> 9) << 10);      // p9 = 0
        P2 v0 = ld4(S, FP(p));
        P2 v1 = ld4(S, FP(p | 512));
        aprx(v0.hi, v1.hi, c15.x, c15.y);
        float pA0 = v0.lo.x*v0.lo.x + v0.lo.y*v0.lo.y;
        float pA1 = v0.hi.x*v0.hi.x + v0.hi.y*v0.hi.y;
        float pB0 = v1.lo.x*v1.lo.x + v1.lo.y*v1.lo.y;
        float pB1 = v1.hi.x*v1.hi.x + v1.hi.y*v1.hi.y;
        float ps = pA0 + pA1 + pB0 + pB1;
        pstot += ps;
        acc[0]  += (pA0 + pA1) - (pB0 + pB1);      // w0  = p9
        acc[15] += (pA0 - pA1) + (pB0 - pB1);      // w15 = pair
        acc[11] += (p & 1)    ? -ps : ps;
        acc[10] += (p & 2)    ? -ps : ps;
        acc[9]  += (p & 4)    ? -ps : ps;
        acc[8]  += (p & 8)    ? -ps : ps;
        acc[7]  += (p & 16)   ? -ps : ps;
        acc[12] += (p & 32)   ? -ps : ps;
        acc[13] += (p & 64)   ? -ps : ps;
        acc[14] += (p & 128)  ? -ps : ps;
        acc[3]  += (p & 256)  ? -ps : ps;
        acc[1]  += (p & 1024) ? -ps : ps;
        acc[2]  += (p & 2048) ? -ps : ps;
    }
    acc[4] = (t & 1) ? -pstot : pstot;
    acc[5] = (t & 2) ? -pstot : pstot;
    acc[6] = (t & 4) ? -pstot : pstot;

    #pragma unroll
    for (int q = 0; q < NQ; q++){
        float v = acc[q];
        #pragma unroll
        for (int off = 16; off > 0; off >>= 1)
            v += __shfl_down_sync(0xffffffffu, v, off);
        acc[q] = v;
    }
    int w = tid >> 5, lane = tid & 31;
    if (lane == 0){
        #pragma unroll
        for (int q = 0; q < NQ; q++) sred[w][q] = acc[q];
    }
    __syncthreads();
    if (tid < NQ){
        float v = 0.f;
        #pragma unroll
        for (int w2 = 0; w2 < 8; w2++) v += sred[w2][tid];
        atomicAdd(&g_expv[b*NQ + tid], v);
    }
    __syncthreads();

    // ---- per-batch last-CTA FC + log_softmax epilogue ----
    if (tid == 0){
        __threadfence();
        int old = atomicAdd(&g_cnt[b], 1);
        lastf = (old == 7);
    }
    __syncthreads();
    if (lastf && tid < 32){
        __threadfence();      // acquire: make all CTAs' expval adds visible
        float f[NQ];
        #pragma unroll
        for (int q = 0; q < NQ; q++) f[q] = g_expv[b*NQ + q];
        float lg = -1e30f;
        if (tid < NC){
            lg = fc_b[tid];
            #pragma unroll
            for (int q = 0; q < NQ; q++) lg = fmaf(fc_w[tid*NQ + q], f[q], lg);
        }
        float mx = lg;
        #pragma unroll
        for (int off = 16; off > 0; off >>= 1)
            mx = fmaxf(mx, __shfl_xor_sync(0xffffffffu, mx, off));
        float e = (tid < NC) ? expf(lg - mx) : 0.f;
        float se = e;
        #pragma unroll
        for (int off = 16; off > 0; off >>= 1)
            se += __shfl_xor_sync(0xffffffffu, se, off);
        if (tid < NC) out[b*NC + tid] = lg - mx - logf(se);
    }
}

extern "C" void kernel_launch(void* const* d_in, const int* in_sizes, int n_in,
                              void* d_out, int out_size){
    const float* x   = (const float*)d_in[0];
    const float* w0  = (const float*)d_in[1];
    const float* x0  = (const float*)d_in[2];
    const float* w1  = (const float*)d_in[3];
    const float* x1  = (const float*)d_in[4];
    const float* fcw = (const float*)d_in[5];
    const float* fcb = (const float*)d_in[6];

    const int smem = NPAIR * sizeof(float4);   // 64 KB
    cudaFuncSetAttribute(p1_init,  cudaFuncAttributeMaxDynamicSharedMemorySize, smem);
    cudaFuncSetAttribute(p2_mid,   cudaFuncAttributeMaxDynamicSharedMemorySize, smem);
    cudaFuncSetAttribute(p3_final, cudaFuncAttributeMaxDynamicSharedMemorySize, smem);

    dim3 grid(8, NB);
    p1_init <<<grid, TPB, smem>>>(x, w0, x0, w1, x1);
    p2_mid  <<<grid, TPB, smem>>>(x, x0, w1, x1);
    p3_final<<<grid, TPB, smem>>>(x1, fcw, fcb, (float*)d_out);
}